// round 5
// baseline (speedup 1.0000x reference)
#include <cuda_runtime.h>
#include <math.h>
#include <stdint.h>

#define Bz 4
#define Tn 2048
#define Dm 1024
#define Hh 16
#define HD 64
#define NHALF 1024   // Tn/2

// Scratch (device globals — allocation-free per harness rules)
__device__ float g_Q[(size_t)Bz * Hh * Tn * HD];
__device__ float g_K[(size_t)Bz * Hh * Tn * HD];
__device__ float g_V[(size_t)Bz * Hh * Tn * HD];
__device__ float g_C[(size_t)Bz * Tn * Dm];

// ---------------------------------------------------------------------------
// 3xTF32 tensor-core GEMM, split-at-store:
//   C = (A[MxK] @ B[KxN] + bias) * scale
// Tiles staged through registers; each element split ONCE into (hi,lo) tf32
// pair stored interleaved as float2 in smem. Inner loop = LDS.64 + HMMA only.
// 128x128 CTA tile, BK=32, 256 threads (8 warps as 2x4), warp tile 64x32.
// Strides (float2 units): A=36, B=132 — both ≡4 mod 16 → conflict-free LDS.64.
// ---------------------------------------------------------------------------
#define ASTR2 36
#define BSTR2 132
#define GEMM_SMEM ((128 * ASTR2 + 32 * BSTR2) * 8)

__device__ __forceinline__ void mma_tf32(float c[4], uint32_t a0, uint32_t a1,
                                         uint32_t a2, uint32_t a3,
                                         uint32_t b0, uint32_t b1) {
    asm volatile(
        "mma.sync.aligned.m16n8k8.row.col.f32.tf32.tf32.f32 "
        "{%0,%1,%2,%3}, {%4,%5,%6,%7}, {%8,%9}, {%0,%1,%2,%3};\n"
        : "+f"(c[0]), "+f"(c[1]), "+f"(c[2]), "+f"(c[3])
        : "r"(a0), "r"(a1), "r"(a2), "r"(a3), "r"(b0), "r"(b1));
}

__device__ __forceinline__ float2 tf32_split(float x) {
    uint32_t hi, lo;
    asm("cvt.rna.tf32.f32 %0, %1;\n" : "=r"(hi) : "f"(x));
    float r = x - __uint_as_float(hi);
    asm("cvt.rna.tf32.f32 %0, %1;\n" : "=r"(lo) : "f"(r));
    return make_float2(__uint_as_float(hi), __uint_as_float(lo));
}

__global__ __launch_bounds__(256, 2)
void gemm_tf32x3(const float* __restrict__ A, const float* __restrict__ Bm,
                 const float* __restrict__ bias, float* __restrict__ C,
                 int M, int N, int K, float scale, int headmode) {
    extern __shared__ float2 sm2[];
    float2* A2 = sm2;                  // 128 x ASTR2
    float2* B2 = sm2 + 128 * ASTR2;    // 32 x BSTR2

    const int tid = threadIdx.x;
    const int m0 = blockIdx.y * 128, n0 = blockIdx.x * 128;
    const int w = tid >> 5, lane = tid & 31;
    const int gid = lane >> 2, tig = lane & 3;
    const int wm = (w & 1) * 64, wn = (w >> 1) * 32;

    float acc[4][4][4];
#pragma unroll
    for (int i = 0; i < 4; i++)
#pragma unroll
        for (int j = 0; j < 4; j++)
#pragma unroll
            for (int c = 0; c < 4; c++) acc[i][j][c] = 0.0f;

    // staging registers: 4 float4 for A, 4 float4 for B
    float4 ra[4], rb[4];

    auto load_regs = [&](int k0) {
#pragma unroll
        for (int i = 0; i < 4; i++) {
            int lin = tid + 256 * i;
            int row = lin >> 3, cg = (lin & 7) * 4;
            ra[i] = *(const float4*)(A + (size_t)(m0 + row) * K + k0 + cg);
        }
#pragma unroll
        for (int i = 0; i < 4; i++) {
            int lin = tid + 256 * i;
            int row = lin >> 5, cg = (lin & 31) * 4;
            rb[i] = *(const float4*)(Bm + (size_t)(k0 + row) * N + n0 + cg);
        }
    };

    auto split_sts = [&]() {
#pragma unroll
        for (int i = 0; i < 4; i++) {
            int lin = tid + 256 * i;
            int row = lin >> 3, cg = (lin & 7) * 4;
            float2* dst = &A2[row * ASTR2 + cg];
            dst[0] = tf32_split(ra[i].x);
            dst[1] = tf32_split(ra[i].y);
            dst[2] = tf32_split(ra[i].z);
            dst[3] = tf32_split(ra[i].w);
        }
#pragma unroll
        for (int i = 0; i < 4; i++) {
            int lin = tid + 256 * i;
            int row = lin >> 5, cg = (lin & 31) * 4;
            float2* dst = &B2[row * BSTR2 + cg];
            dst[0] = tf32_split(rb[i].x);
            dst[1] = tf32_split(rb[i].y);
            dst[2] = tf32_split(rb[i].z);
            dst[3] = tf32_split(rb[i].w);
        }
    };

    load_regs(0);
    split_sts();

    for (int k0 = 0; k0 < K; k0 += 32) {
        __syncthreads();               // tile visible
        const bool more = (k0 + 32 < K);
        if (more) load_regs(k0 + 32);  // LDG latency hidden by compute

#pragma unroll
        for (int kk = 0; kk < 4; kk++) {
            const int k = kk * 8;
            float2 bfr[4][2];
#pragma unroll
            for (int nt = 0; nt < 4; nt++) {
                bfr[nt][0] = B2[(k + tig) * BSTR2 + wn + nt * 8 + gid];
                bfr[nt][1] = B2[(k + tig + 4) * BSTR2 + wn + nt * 8 + gid];
            }
#pragma unroll
            for (int mt = 0; mt < 4; mt++) {
                const int r0 = (wm + mt * 16 + gid) * ASTR2;
                float2 a0 = A2[r0 + k + tig];
                float2 a1 = A2[r0 + 8 * ASTR2 + k + tig];
                float2 a2 = A2[r0 + k + tig + 4];
                float2 a3 = A2[r0 + 8 * ASTR2 + k + tig + 4];
#pragma unroll
                for (int nt = 0; nt < 4; nt++) {
                    mma_tf32(acc[mt][nt],
                             __float_as_uint(a0.x), __float_as_uint(a1.x),
                             __float_as_uint(a2.x), __float_as_uint(a3.x),
                             __float_as_uint(bfr[nt][0].x), __float_as_uint(bfr[nt][1].x));
                    mma_tf32(acc[mt][nt],
                             __float_as_uint(a0.x), __float_as_uint(a1.x),
                             __float_as_uint(a2.x), __float_as_uint(a3.x),
                             __float_as_uint(bfr[nt][0].y), __float_as_uint(bfr[nt][1].y));
                    mma_tf32(acc[mt][nt],
                             __float_as_uint(a0.y), __float_as_uint(a1.y),
                             __float_as_uint(a2.y), __float_as_uint(a3.y),
                             __float_as_uint(bfr[nt][0].x), __float_as_uint(bfr[nt][1].x));
                }
            }
        }

        if (more) {
            __syncthreads();           // all reads done before overwrite
            split_sts();
        }
    }

    // Epilogue
#pragma unroll
    for (int mt = 0; mt < 4; mt++) {
#pragma unroll
        for (int rr = 0; rr < 2; rr++) {
            int m = m0 + wm + mt * 16 + gid + rr * 8;
#pragma unroll
            for (int nt = 0; nt < 4; nt++) {
                int col = n0 + wn + nt * 8 + tig * 2;
                float v0 = (acc[mt][nt][rr * 2 + 0] + bias[col]) * scale;
                float v1 = (acc[mt][nt][rr * 2 + 1] + bias[col + 1]) * scale;
                if (headmode) {
                    int bb = m >> 11, t = m & (Tn - 1);
                    int h = col >> 6, dd = col & 63;
                    float2* dst = (float2*)&C[((((size_t)bb * Hh + h) * Tn + t) << 6) + dd];
                    *dst = make_float2(v0, v1);
                } else {
                    *(float2*)&C[(size_t)m * N + col] = make_float2(v0, v1);
                }
            }
        }
    }
}

// ---------------------------------------------------------------------------
// BD3LM mask predicate
// ---------------------------------------------------------------------------
__device__ __forceinline__ bool can_attend(int q, int kv, int bs) {
    bool x0q = q >= NHALF, x0k = kv >= NHALF;
    int bq = (x0q ? q - NHALF : q) / bs;
    int bk = (x0k ? kv - NHALF : kv) / bs;
    return (bq == bk && x0q == x0k) ||
           (bq > bk && x0k && !x0q) ||
           (bq >= bk && x0k && x0q);
}

// ---------------------------------------------------------------------------
// Fused masked flash attention: 64q x 64k tiles, tile-level skipping.
// qt reversed so heavy tiles (long history) launch first.
// ---------------------------------------------------------------------------
#define ATTN_SMEM ((64 * 65 * 3 + 64 * 64) * 4)

__global__ __launch_bounds__(256)
void attn_kernel(const float* __restrict__ Q, const float* __restrict__ K,
                 const float* __restrict__ V, float* __restrict__ C,
                 const int* __restrict__ bs_ptr) {
    extern __shared__ float smA[];
    float* Qs = smA;                // 64*65
    float* Ks = Qs + 64 * 65;       // 64*65
    float* Vs = Ks + 64 * 65;       // 64*64
    float* Ps = Vs + 64 * 64;       // 64*65

    int bs = 4;
    if (bs_ptr) {
        int v = *bs_ptr;
        if (v >= 1 && v <= Tn) bs = v;
    }

    const int tid = threadIdx.x;
    const int qt = gridDim.x - 1 - blockIdx.x;   // heavy tiles first
    const int h = blockIdx.y, b = blockIdx.z;
    const int q0 = qt * 64;
    const size_t base = ((size_t)b * Hh + h) * Tn * HD;

    {
        int r = tid >> 2, cs = (tid & 3) * 16;
        const float* src = Q + base + (size_t)(q0 + r) * HD + cs;
#pragma unroll
        for (int i = 0; i < 4; i++) {
            float4 v4 = *(const float4*)(src + i * 4);
            Qs[r * 65 + cs + i * 4 + 0] = v4.x;
            Qs[r * 65 + cs + i * 4 + 1] = v4.y;
            Qs[r * 65 + cs + i * 4 + 2] = v4.z;
            Qs[r * 65 + cs + i * 4 + 3] = v4.w;
        }
    }

    const int ty = tid >> 4, tx = tid & 15;
    float m_i[4], l_i[4], acc[4][4];
#pragma unroll
    for (int i = 0; i < 4; i++) {
        m_i[i] = -1e30f;
        l_i[i] = 0.0f;
#pragma unroll
        for (int j = 0; j < 4; j++) acc[i][j] = 0.0f;
    }

    const bool x0q = q0 >= NHALF;
    const int bqlo = (x0q ? q0 - NHALF : q0) / bs;
    const int bqhi = (x0q ? q0 + 63 - NHALF : q0 + 63) / bs;

    for (int kt = 0; kt < Tn / 64; kt++) {
        const int k0 = kt * 64;
        {
            bool x0k = k0 >= NHALF;
            int bklo = (x0k ? k0 - NHALF : k0) / bs;
            int bkhi = (x0k ? k0 + 63 - NHALF : k0 + 63) / bs;
            bool any = (x0q == x0k && bqhi >= bklo && bkhi >= bqlo) ||
                       (!x0q && x0k && bqhi > bklo) ||
                       (x0q && x0k && bqhi >= bklo);
            if (!any) continue;
        }
        __syncthreads();
        {
            int r = tid >> 2, cs = (tid & 3) * 16;
            const float* ksrc = K + base + (size_t)(k0 + r) * HD + cs;
            const float* vsrc = V + base + (size_t)(k0 + r) * HD + cs;
#pragma unroll
            for (int i = 0; i < 4; i++) {
                float4 k4 = *(const float4*)(ksrc + i * 4);
                Ks[r * 65 + cs + i * 4 + 0] = k4.x;
                Ks[r * 65 + cs + i * 4 + 1] = k4.y;
                Ks[r * 65 + cs + i * 4 + 2] = k4.z;
                Ks[r * 65 + cs + i * 4 + 3] = k4.w;
                *(float4*)(Vs + r * 64 + cs + i * 4) = *(const float4*)(vsrc + i * 4);
            }
        }
        __syncthreads();

        float s[4][4];
#pragma unroll
        for (int i = 0; i < 4; i++)
#pragma unroll
            for (int j = 0; j < 4; j++) s[i][j] = 0.0f;
#pragma unroll 8
        for (int d = 0; d < 64; d++) {
            float a[4], bb[4];
#pragma unroll
            for (int i = 0; i < 4; i++) a[i] = Qs[(ty * 4 + i) * 65 + d];
#pragma unroll
            for (int j = 0; j < 4; j++) bb[j] = Ks[(tx * 4 + j) * 65 + d];
#pragma unroll
            for (int i = 0; i < 4; i++)
#pragma unroll
                for (int j = 0; j < 4; j++) s[i][j] += a[i] * bb[j];
        }

#pragma unroll
        for (int i = 0; i < 4; i++) {
            int q = q0 + ty * 4 + i;
#pragma unroll
            for (int j = 0; j < 4; j++) {
                int kv = k0 + tx * 4 + j;
                if (!can_attend(q, kv, bs)) s[i][j] = -1e30f;
            }
        }

#pragma unroll
        for (int i = 0; i < 4; i++) {
            float rm = fmaxf(fmaxf(s[i][0], s[i][1]), fmaxf(s[i][2], s[i][3]));
            rm = fmaxf(rm, __shfl_xor_sync(0xffffffffu, rm, 1));
            rm = fmaxf(rm, __shfl_xor_sync(0xffffffffu, rm, 2));
            rm = fmaxf(rm, __shfl_xor_sync(0xffffffffu, rm, 4));
            rm = fmaxf(rm, __shfl_xor_sync(0xffffffffu, rm, 8));
            float mnew = fmaxf(m_i[i], rm);
            float rs = 0.0f;
#pragma unroll
            for (int j = 0; j < 4; j++) {
                s[i][j] = __expf(s[i][j] - mnew);
                rs += s[i][j];
            }
            rs += __shfl_xor_sync(0xffffffffu, rs, 1);
            rs += __shfl_xor_sync(0xffffffffu, rs, 2);
            rs += __shfl_xor_sync(0xffffffffu, rs, 4);
            rs += __shfl_xor_sync(0xffffffffu, rs, 8);
            float f = __expf(m_i[i] - mnew);
            l_i[i] = l_i[i] * f + rs;
            m_i[i] = mnew;
#pragma unroll
            for (int j = 0; j < 4; j++) {
                acc[i][j] *= f;
                Ps[(ty * 4 + i) * 65 + tx * 4 + j] = s[i][j];
            }
        }
        __syncthreads();

#pragma unroll 8
        for (int k = 0; k < 64; k++) {
            float a[4], bb[4];
#pragma unroll
            for (int i = 0; i < 4; i++) a[i] = Ps[(ty * 4 + i) * 65 + k];
#pragma unroll
            for (int j = 0; j < 4; j++) bb[j] = Vs[k * 64 + tx * 4 + j];
#pragma unroll
            for (int i = 0; i < 4; i++)
#pragma unroll
                for (int j = 0; j < 4; j++) acc[i][j] += a[i] * bb[j];
        }
    }

#pragma unroll
    for (int i = 0; i < 4; i++) {
        float inv = 1.0f / l_i[i];
        int t = q0 + ty * 4 + i;
#pragma unroll
        for (int j = 0; j < 4; j++) {
            C[((size_t)b * Tn + t) * Dm + h * HD + tx * 4 + j] = acc[i][j] * inv;
        }
    }
}

// ---------------------------------------------------------------------------
extern "C" void kernel_launch(void* const* d_in, const int* in_sizes, int n_in,
                              void* d_out, int out_size) {
    const float* x  = (const float*)d_in[0];
    const float* Wq = (const float*)d_in[1];
    const float* bq = (const float*)d_in[2];
    const float* Wk = (const float*)d_in[3];
    const float* bk = (const float*)d_in[4];
    const float* Wv = (const float*)d_in[5];
    const float* bv = (const float*)d_in[6];
    const float* Wo = (const float*)d_in[7];
    const float* bo = (const float*)d_in[8];
    const int* bsp  = (n_in > 9) ? (const int*)d_in[9] : nullptr;

    float *qb, *kb, *vb, *cb;
    cudaGetSymbolAddress((void**)&qb, g_Q);
    cudaGetSymbolAddress((void**)&kb, g_K);
    cudaGetSymbolAddress((void**)&vb, g_V);
    cudaGetSymbolAddress((void**)&cb, g_C);

    cudaFuncSetAttribute(attn_kernel, cudaFuncAttributeMaxDynamicSharedMemorySize,
                         ATTN_SMEM);
    cudaFuncSetAttribute(gemm_tf32x3, cudaFuncAttributeMaxDynamicSharedMemorySize,
                         GEMM_SMEM);

    const int M = Bz * Tn;
    dim3 gg(Dm / 128, M / 128);
    const float qscale = 0.125f;  // hd^-0.5, hd=64

    gemm_tf32x3<<<gg, 256, GEMM_SMEM>>>(x, Wq, bq, qb, M, Dm, Dm, qscale, 1);
    gemm_tf32x3<<<gg, 256, GEMM_SMEM>>>(x, Wk, bk, kb, M, Dm, Dm, 1.0f, 1);
    gemm_tf32x3<<<gg, 256, GEMM_SMEM>>>(x, Wv, bv, vb, M, Dm, Dm, 1.0f, 1);

    dim3 ga(Tn / 64, Hh, Bz);
    attn_kernel<<<ga, 256, ATTN_SMEM>>>(qb, kb, vb, cb, bsp);

    gemm_tf32x3<<<gg, 256, GEMM_SMEM>>>(cb, Wo, bo, (float*)d_out, M, Dm, Dm, 1.0f, 0);
}

// round 6
// speedup vs baseline: 1.1253x; 1.1253x over previous
#include <cuda_runtime.h>
#include <math.h>
#include <stdint.h>

#define Bz 4
#define Tn 2048
#define Dm 1024
#define Hh 16
#define HD 64
#define NHALF 1024   // Tn/2

// Scratch (device globals — allocation-free per harness rules)
__device__ float g_Q[(size_t)Bz * Hh * Tn * HD];
__device__ float g_K[(size_t)Bz * Hh * Tn * HD];
__device__ float g_V[(size_t)Bz * Hh * Tn * HD];
__device__ float g_C[(size_t)Bz * Tn * Dm];

// Pre-split (hi,lo) interleaved buffers
__device__ float g_xs[2 * (size_t)Bz * Tn * Dm];
__device__ float g_cs[2 * (size_t)Bz * Tn * Dm];
__device__ float g_wq[2 * (size_t)Dm * Dm];
__device__ float g_wk[2 * (size_t)Dm * Dm];
__device__ float g_wv[2 * (size_t)Dm * Dm];
__device__ float g_wo[2 * (size_t)Dm * Dm];

// ---------------------------------------------------------------------------
// tf32 Dekker split: x = hi + lo, both exactly representable in tf32.
// ---------------------------------------------------------------------------
__device__ __forceinline__ float2 tf32_split(float x) {
    uint32_t hi, lo;
    asm("cvt.rna.tf32.f32 %0, %1;\n" : "=r"(hi) : "f"(x));
    float r = x - __uint_as_float(hi);
    asm("cvt.rna.tf32.f32 %0, %1;\n" : "=r"(lo) : "f"(r));
    return make_float2(__uint_as_float(hi), __uint_as_float(lo));
}

// Elementwise pre-split: in[n4] float4 -> out[2*n4] float4 (hi,lo interleaved)
__global__ __launch_bounds__(256)
void split_kernel(const float4* __restrict__ in, float4* __restrict__ out, int n4) {
    int i = blockIdx.x * blockDim.x + threadIdx.x;
    if (i >= n4) return;
    float4 v = in[i];
    float2 s0 = tf32_split(v.x), s1 = tf32_split(v.y);
    float2 s2 = tf32_split(v.z), s3 = tf32_split(v.w);
    out[2 * i + 0] = make_float4(s0.x, s0.y, s1.x, s1.y);
    out[2 * i + 1] = make_float4(s2.x, s2.y, s3.x, s3.y);
}

// ---------------------------------------------------------------------------
// 3xTF32 GEMM on pre-split operands: C = (A @ B + bias) * scale
// A2/B2 are interleaved (hi,lo) float2 arrays, logical shapes MxK / KxN.
// 128x128 CTA tile, BK=32, 512 threads (16 warps as 4x4), warp tile 32x32.
// cp.async double-buffered; inner loop pure LDS.64 + HMMA (no cvt).
// ---------------------------------------------------------------------------
#define ASTR2 36
#define BSTR2 132
#define BUFSZ (128 * ASTR2 + 32 * BSTR2)
#define GEMM_SMEM (BUFSZ * 2 * 8)

__device__ __forceinline__ void cp16(uint32_t dst, const void* src) {
    asm volatile("cp.async.cg.shared.global [%0], [%1], 16;\n" :: "r"(dst), "l"(src));
}

__device__ __forceinline__ void mma_tf32(float c[4], uint32_t a0, uint32_t a1,
                                         uint32_t a2, uint32_t a3,
                                         uint32_t b0, uint32_t b1) {
    asm volatile(
        "mma.sync.aligned.m16n8k8.row.col.f32.tf32.tf32.f32 "
        "{%0,%1,%2,%3}, {%4,%5,%6,%7}, {%8,%9}, {%0,%1,%2,%3};\n"
        : "+f"(c[0]), "+f"(c[1]), "+f"(c[2]), "+f"(c[3])
        : "r"(a0), "r"(a1), "r"(a2), "r"(a3), "r"(b0), "r"(b1));
}

__global__ __launch_bounds__(512, 1)
void gemm_pre(const float2* __restrict__ A2, const float2* __restrict__ B2,
              const float* __restrict__ bias, float* __restrict__ C,
              int M, int N, int K, float scale, int headmode) {
    extern __shared__ float2 sm2[];

    const int tid = threadIdx.x;
    const int m0 = blockIdx.y * 128, n0 = blockIdx.x * 128;
    const int w = tid >> 5, lane = tid & 31;
    const int gid = lane >> 2, tig = lane & 3;
    const int wm = (w & 3) * 32, wn = (w >> 2) * 32;

    float acc[2][4][4];
#pragma unroll
    for (int i = 0; i < 2; i++)
#pragma unroll
        for (int j = 0; j < 4; j++)
#pragma unroll
            for (int c = 0; c < 4; c++) acc[i][j][c] = 0.0f;

    uint32_t abase[2], bbase[2];
#pragma unroll
    for (int s = 0; s < 2; s++) {
        abase[s] = (uint32_t)__cvta_generic_to_shared(sm2 + s * BUFSZ);
        bbase[s] = (uint32_t)__cvta_generic_to_shared(sm2 + s * BUFSZ + 128 * ASTR2);
    }

    auto issue_tile = [&](int k0, int s) {
        // A tile: 128x32 float2 = 2048 16B-chunks (2 elts each), 4/thread
#pragma unroll
        for (int i = 0; i < 4; i++) {
            int lin = tid + 512 * i;
            int row = lin >> 4, cc = (lin & 15) * 2;
            cp16(abase[s] + (row * ASTR2 + cc) * 8,
                 A2 + (size_t)(m0 + row) * K + k0 + cc);
        }
        // B tile: 32x128 float2 = 2048 chunks, 4/thread
#pragma unroll
        for (int i = 0; i < 4; i++) {
            int lin = tid + 512 * i;
            int row = lin >> 6, cc = (lin & 63) * 2;
            cp16(bbase[s] + (row * BSTR2 + cc) * 8,
                 B2 + (size_t)(k0 + row) * N + n0 + cc);
        }
        asm volatile("cp.async.commit_group;\n");
    };

    issue_tile(0, 0);
    int cur = 0;

    for (int k0 = 0; k0 < K; k0 += 32) {
        if (k0 + 32 < K) {
            issue_tile(k0 + 32, cur ^ 1);
            asm volatile("cp.async.wait_group 1;\n");
        } else {
            asm volatile("cp.async.wait_group 0;\n");
        }
        __syncthreads();

        const float2* As = sm2 + cur * BUFSZ;
        const float2* Bs = As + 128 * ASTR2;
#pragma unroll
        for (int kk = 0; kk < 4; kk++) {
            const int k = kk * 8;
            float2 b0[4], b1[4];
#pragma unroll
            for (int nt = 0; nt < 4; nt++) {
                b0[nt] = Bs[(k + tig) * BSTR2 + wn + nt * 8 + gid];
                b1[nt] = Bs[(k + tig + 4) * BSTR2 + wn + nt * 8 + gid];
            }
#pragma unroll
            for (int mt = 0; mt < 2; mt++) {
                const int r0 = (wm + mt * 16 + gid) * ASTR2;
                float2 a0 = As[r0 + k + tig];
                float2 a1 = As[r0 + 8 * ASTR2 + k + tig];
                float2 a2 = As[r0 + k + tig + 4];
                float2 a3 = As[r0 + 8 * ASTR2 + k + tig + 4];
#pragma unroll
                for (int nt = 0; nt < 4; nt++) {
                    mma_tf32(acc[mt][nt],
                             __float_as_uint(a0.x), __float_as_uint(a1.x),
                             __float_as_uint(a2.x), __float_as_uint(a3.x),
                             __float_as_uint(b0[nt].x), __float_as_uint(b1[nt].x));
                    mma_tf32(acc[mt][nt],
                             __float_as_uint(a0.x), __float_as_uint(a1.x),
                             __float_as_uint(a2.x), __float_as_uint(a3.x),
                             __float_as_uint(b0[nt].y), __float_as_uint(b1[nt].y));
                    mma_tf32(acc[mt][nt],
                             __float_as_uint(a0.y), __float_as_uint(a1.y),
                             __float_as_uint(a2.y), __float_as_uint(a3.y),
                             __float_as_uint(b0[nt].x), __float_as_uint(b1[nt].x));
                }
            }
        }
        __syncthreads();
        cur ^= 1;
    }

    // Epilogue
#pragma unroll
    for (int mt = 0; mt < 2; mt++) {
#pragma unroll
        for (int rr = 0; rr < 2; rr++) {
            int m = m0 + wm + mt * 16 + gid + rr * 8;
#pragma unroll
            for (int nt = 0; nt < 4; nt++) {
                int col = n0 + wn + nt * 8 + tig * 2;
                float v0 = (acc[mt][nt][rr * 2 + 0] + bias[col]) * scale;
                float v1 = (acc[mt][nt][rr * 2 + 1] + bias[col + 1]) * scale;
                if (headmode) {
                    int bb = m >> 11, t = m & (Tn - 1);
                    int h = col >> 6, dd = col & 63;
                    float2* dst = (float2*)&C[((((size_t)bb * Hh + h) * Tn + t) << 6) + dd];
                    *dst = make_float2(v0, v1);
                } else {
                    *(float2*)&C[(size_t)m * N + col] = make_float2(v0, v1);
                }
            }
        }
    }
}

// ---------------------------------------------------------------------------
// BD3LM mask predicate
// ---------------------------------------------------------------------------
__device__ __forceinline__ bool can_attend(int q, int kv, int bs) {
    bool x0q = q >= NHALF, x0k = kv >= NHALF;
    int bq = (x0q ? q - NHALF : q) / bs;
    int bk = (x0k ? kv - NHALF : kv) / bs;
    return (bq == bk && x0q == x0k) ||
           (bq > bk && x0k && !x0q) ||
           (bq >= bk && x0k && x0q);
}

// ---------------------------------------------------------------------------
// Fused masked flash attention: 64q x 64k tiles, tile-level skipping.
// ---------------------------------------------------------------------------
#define ATTN_SMEM ((64 * 65 * 3 + 64 * 64) * 4)

__global__ __launch_bounds__(256)
void attn_kernel(const float* __restrict__ Q, const float* __restrict__ K,
                 const float* __restrict__ V, float* __restrict__ C,
                 const int* __restrict__ bs_ptr) {
    extern __shared__ float smA[];
    float* Qs = smA;                // 64*65
    float* Ks = Qs + 64 * 65;       // 64*65
    float* Vs = Ks + 64 * 65;       // 64*64
    float* Ps = Vs + 64 * 64;       // 64*65

    int bs = 4;
    if (bs_ptr) {
        int v = *bs_ptr;
        if (v >= 1 && v <= Tn) bs = v;
    }

    const int tid = threadIdx.x;
    const int qt = gridDim.x - 1 - blockIdx.x;   // heavy tiles first
    const int h = blockIdx.y, b = blockIdx.z;
    const int q0 = qt * 64;
    const size_t base = ((size_t)b * Hh + h) * Tn * HD;

    {
        int r = tid >> 2, cs = (tid & 3) * 16;
        const float* src = Q + base + (size_t)(q0 + r) * HD + cs;
#pragma unroll
        for (int i = 0; i < 4; i++) {
            float4 v4 = *(const float4*)(src + i * 4);
            Qs[r * 65 + cs + i * 4 + 0] = v4.x;
            Qs[r * 65 + cs + i * 4 + 1] = v4.y;
            Qs[r * 65 + cs + i * 4 + 2] = v4.z;
            Qs[r * 65 + cs + i * 4 + 3] = v4.w;
        }
    }

    const int ty = tid >> 4, tx = tid & 15;
    float m_i[4], l_i[4], acc[4][4];
#pragma unroll
    for (int i = 0; i < 4; i++) {
        m_i[i] = -1e30f;
        l_i[i] = 0.0f;
#pragma unroll
        for (int j = 0; j < 4; j++) acc[i][j] = 0.0f;
    }

    const bool x0q = q0 >= NHALF;
    const int bqlo = (x0q ? q0 - NHALF : q0) / bs;
    const int bqhi = (x0q ? q0 + 63 - NHALF : q0 + 63) / bs;

    for (int kt = 0; kt < Tn / 64; kt++) {
        const int k0 = kt * 64;
        {
            bool x0k = k0 >= NHALF;
            int bklo = (x0k ? k0 - NHALF : k0) / bs;
            int bkhi = (x0k ? k0 + 63 - NHALF : k0 + 63) / bs;
            bool any = (x0q == x0k && bqhi >= bklo && bkhi >= bqlo) ||
                       (!x0q && x0k && bqhi > bklo) ||
                       (x0q && x0k && bqhi >= bklo);
            if (!any) continue;
        }
        __syncthreads();
        {
            int r = tid >> 2, cs = (tid & 3) * 16;
            const float* ksrc = K + base + (size_t)(k0 + r) * HD + cs;
            const float* vsrc = V + base + (size_t)(k0 + r) * HD + cs;
#pragma unroll
            for (int i = 0; i < 4; i++) {
                float4 k4 = *(const float4*)(ksrc + i * 4);
                Ks[r * 65 + cs + i * 4 + 0] = k4.x;
                Ks[r * 65 + cs + i * 4 + 1] = k4.y;
                Ks[r * 65 + cs + i * 4 + 2] = k4.z;
                Ks[r * 65 + cs + i * 4 + 3] = k4.w;
                *(float4*)(Vs + r * 64 + cs + i * 4) = *(const float4*)(vsrc + i * 4);
            }
        }
        __syncthreads();

        float s[4][4];
#pragma unroll
        for (int i = 0; i < 4; i++)
#pragma unroll
            for (int j = 0; j < 4; j++) s[i][j] = 0.0f;
#pragma unroll 8
        for (int d = 0; d < 64; d++) {
            float a[4], bb[4];
#pragma unroll
            for (int i = 0; i < 4; i++) a[i] = Qs[(ty * 4 + i) * 65 + d];
#pragma unroll
            for (int j = 0; j < 4; j++) bb[j] = Ks[(tx * 4 + j) * 65 + d];
#pragma unroll
            for (int i = 0; i < 4; i++)
#pragma unroll
                for (int j = 0; j < 4; j++) s[i][j] += a[i] * bb[j];
        }

#pragma unroll
        for (int i = 0; i < 4; i++) {
            int q = q0 + ty * 4 + i;
#pragma unroll
            for (int j = 0; j < 4; j++) {
                int kv = k0 + tx * 4 + j;
                if (!can_attend(q, kv, bs)) s[i][j] = -1e30f;
            }
        }

#pragma unroll
        for (int i = 0; i < 4; i++) {
            float rm = fmaxf(fmaxf(s[i][0], s[i][1]), fmaxf(s[i][2], s[i][3]));
            rm = fmaxf(rm, __shfl_xor_sync(0xffffffffu, rm, 1));
            rm = fmaxf(rm, __shfl_xor_sync(0xffffffffu, rm, 2));
            rm = fmaxf(rm, __shfl_xor_sync(0xffffffffu, rm, 4));
            rm = fmaxf(rm, __shfl_xor_sync(0xffffffffu, rm, 8));
            float mnew = fmaxf(m_i[i], rm);
            float rs = 0.0f;
#pragma unroll
            for (int j = 0; j < 4; j++) {
                s[i][j] = __expf(s[i][j] - mnew);
                rs += s[i][j];
            }
            rs += __shfl_xor_sync(0xffffffffu, rs, 1);
            rs += __shfl_xor_sync(0xffffffffu, rs, 2);
            rs += __shfl_xor_sync(0xffffffffu, rs, 4);
            rs += __shfl_xor_sync(0xffffffffu, rs, 8);
            float f = __expf(m_i[i] - mnew);
            l_i[i] = l_i[i] * f + rs;
            m_i[i] = mnew;
#pragma unroll
            for (int j = 0; j < 4; j++) {
                acc[i][j] *= f;
                Ps[(ty * 4 + i) * 65 + tx * 4 + j] = s[i][j];
            }
        }
        __syncthreads();

#pragma unroll 8
        for (int k = 0; k < 64; k++) {
            float a[4], bb[4];
#pragma unroll
            for (int i = 0; i < 4; i++) a[i] = Ps[(ty * 4 + i) * 65 + k];
#pragma unroll
            for (int j = 0; j < 4; j++) bb[j] = Vs[k * 64 + tx * 4 + j];
#pragma unroll
            for (int i = 0; i < 4; i++)
#pragma unroll
                for (int j = 0; j < 4; j++) acc[i][j] += a[i] * bb[j];
        }
    }

#pragma unroll
    for (int i = 0; i < 4; i++) {
        float inv = 1.0f / l_i[i];
        int t = q0 + ty * 4 + i;
#pragma unroll
        for (int j = 0; j < 4; j++) {
            C[((size_t)b * Tn + t) * Dm + h * HD + tx * 4 + j] = acc[i][j] * inv;
        }
    }
}

// ---------------------------------------------------------------------------
extern "C" void kernel_launch(void* const* d_in, const int* in_sizes, int n_in,
                              void* d_out, int out_size) {
    const float* x  = (const float*)d_in[0];
    const float* Wq = (const float*)d_in[1];
    const float* bq = (const float*)d_in[2];
    const float* Wk = (const float*)d_in[3];
    const float* bk = (const float*)d_in[4];
    const float* Wv = (const float*)d_in[5];
    const float* bv = (const float*)d_in[6];
    const float* Wo = (const float*)d_in[7];
    const float* bo = (const float*)d_in[8];
    const int* bsp  = (n_in > 9) ? (const int*)d_in[9] : nullptr;

    float *qb, *kb, *vb, *cb;
    float *xs, *cs, *wq2, *wk2, *wv2, *wo2;
    cudaGetSymbolAddress((void**)&qb, g_Q);
    cudaGetSymbolAddress((void**)&kb, g_K);
    cudaGetSymbolAddress((void**)&vb, g_V);
    cudaGetSymbolAddress((void**)&cb, g_C);
    cudaGetSymbolAddress((void**)&xs, g_xs);
    cudaGetSymbolAddress((void**)&cs, g_cs);
    cudaGetSymbolAddress((void**)&wq2, g_wq);
    cudaGetSymbolAddress((void**)&wk2, g_wk);
    cudaGetSymbolAddress((void**)&wv2, g_wv);
    cudaGetSymbolAddress((void**)&wo2, g_wo);

    cudaFuncSetAttribute(attn_kernel, cudaFuncAttributeMaxDynamicSharedMemorySize,
                         ATTN_SMEM);
    cudaFuncSetAttribute(gemm_pre, cudaFuncAttributeMaxDynamicSharedMemorySize,
                         GEMM_SMEM);

    const int M = Bz * Tn;
    const int nx4 = Bz * Tn * Dm / 4;
    const int nw4 = Dm * Dm / 4;

    // Pre-split operands into (hi,lo) interleaved buffers
    split_kernel<<<(nx4 + 255) / 256, 256>>>((const float4*)x, (float4*)xs, nx4);
    split_kernel<<<(nw4 + 255) / 256, 256>>>((const float4*)Wq, (float4*)wq2, nw4);
    split_kernel<<<(nw4 + 255) / 256, 256>>>((const float4*)Wk, (float4*)wk2, nw4);
    split_kernel<<<(nw4 + 255) / 256, 256>>>((const float4*)Wv, (float4*)wv2, nw4);
    split_kernel<<<(nw4 + 255) / 256, 256>>>((const float4*)Wo, (float4*)wo2, nw4);

    dim3 gg(Dm / 128, M / 128);
    const float qscale = 0.125f;  // hd^-0.5, hd=64

    gemm_pre<<<gg, 512, GEMM_SMEM>>>((const float2*)xs, (const float2*)wq2, bq, qb,
                                     M, Dm, Dm, qscale, 1);
    gemm_pre<<<gg, 512, GEMM_SMEM>>>((const float2*)xs, (const float2*)wk2, bk, kb,
                                     M, Dm, Dm, 1.0f, 1);
    gemm_pre<<<gg, 512, GEMM_SMEM>>>((const float2*)xs, (const float2*)wv2, bv, vb,
                                     M, Dm, Dm, 1.0f, 1);

    dim3 ga(Tn / 64, Hh, Bz);
    attn_kernel<<<ga, 256, ATTN_SMEM>>>(qb, kb, vb, cb, bsp);

    split_kernel<<<(nx4 + 255) / 256, 256>>>((const float4*)cb, (float4*)cs, nx4);
    gemm_pre<<<gg, 512, GEMM_SMEM>>>((const float2*)cs, (const float2*)wo2, bo,
                                     (float*)d_out, M, Dm, Dm, 1.0f, 0);
}

// round 7
// speedup vs baseline: 1.7726x; 1.5753x over previous
#include <cuda_runtime.h>
#include <cuda_bf16.h>
#include <math.h>
#include <stdint.h>

#define Bz 4
#define Tn 2048
#define Dm 1024
#define Hh 16
#define HD 64
#define NHALF 1024   // Tn/2

// Scratch (device globals — allocation-free per harness rules)
__device__ float g_Q[(size_t)Bz * Hh * Tn * HD];
__device__ float g_K[(size_t)Bz * Hh * Tn * HD];
__device__ float g_V[(size_t)Bz * Hh * Tn * HD];
__device__ float g_C[(size_t)Bz * Tn * Dm];

// bf16 split planes
__device__ __nv_bfloat16 g_xhi[(size_t)Bz * Tn * Dm];
__device__ __nv_bfloat16 g_xlo[(size_t)Bz * Tn * Dm];
__device__ __nv_bfloat16 g_chi[(size_t)Bz * Tn * Dm];
__device__ __nv_bfloat16 g_clo[(size_t)Bz * Tn * Dm];
// weights, TRANSPOSED to [N][K], split planes
__device__ __nv_bfloat16 g_wqh[(size_t)Dm * Dm];
__device__ __nv_bfloat16 g_wql[(size_t)Dm * Dm];
__device__ __nv_bfloat16 g_wkh[(size_t)Dm * Dm];
__device__ __nv_bfloat16 g_wkl[(size_t)Dm * Dm];
__device__ __nv_bfloat16 g_wvh[(size_t)Dm * Dm];
__device__ __nv_bfloat16 g_wvl[(size_t)Dm * Dm];
__device__ __nv_bfloat16 g_woh[(size_t)Dm * Dm];
__device__ __nv_bfloat16 g_wol[(size_t)Dm * Dm];

// ---------------------------------------------------------------------------
// bf16 Dekker split helpers
// ---------------------------------------------------------------------------
__device__ __forceinline__ void bf16_split(float x, __nv_bfloat16& h, __nv_bfloat16& l) {
    h = __float2bfloat16_rn(x);
    l = __float2bfloat16_rn(x - __bfloat162float(h));
}

// Row-major split: in[n4] float4 -> hi/lo bf16 planes (8B vector stores)
__global__ __launch_bounds__(256)
void split_rows(const float4* __restrict__ in, __nv_bfloat16* __restrict__ hi,
                __nv_bfloat16* __restrict__ lo, int n4) {
    int i = blockIdx.x * blockDim.x + threadIdx.x;
    if (i >= n4) return;
    float4 v = in[i];
    __nv_bfloat16 h[4], l[4];
    bf16_split(v.x, h[0], l[0]);
    bf16_split(v.y, h[1], l[1]);
    bf16_split(v.z, h[2], l[2]);
    bf16_split(v.w, h[3], l[3]);
    ushort4 hv = make_ushort4(__bfloat16_as_ushort(h[0]), __bfloat16_as_ushort(h[1]),
                              __bfloat16_as_ushort(h[2]), __bfloat16_as_ushort(h[3]));
    ushort4 lv = make_ushort4(__bfloat16_as_ushort(l[0]), __bfloat16_as_ushort(l[1]),
                              __bfloat16_as_ushort(l[2]), __bfloat16_as_ushort(l[3]));
    ((ushort4*)hi)[i] = hv;
    ((ushort4*)lo)[i] = lv;
}

// Transpose + split: W[K][N] fp32 -> WThi[N][K], WTlo[N][K] bf16
__global__ __launch_bounds__(256)
void split_T(const float* __restrict__ W, __nv_bfloat16* __restrict__ hi,
             __nv_bfloat16* __restrict__ lo) {
    __shared__ float tile[32][33];
    int tx = threadIdx.x, ty = threadIdx.y;       // 32 x 8
    int nb = blockIdx.x * 32, kb = blockIdx.y * 32;
#pragma unroll
    for (int j = 0; j < 32; j += 8)
        tile[ty + j][tx] = W[(size_t)(kb + ty + j) * Dm + nb + tx];
    __syncthreads();
#pragma unroll
    for (int j = 0; j < 32; j += 8) {
        int n = nb + ty + j, k = kb + tx;
        float v = tile[tx][ty + j];
        __nv_bfloat16 h, l;
        bf16_split(v, h, l);
        hi[(size_t)n * Dm + k] = h;
        lo[(size_t)n * Dm + k] = l;
    }
}

// ---------------------------------------------------------------------------
// 3x-bf16 GEMM: C = (A @ B + bias) * scale with A=Ahi+Alo, B=Bhi+Blo planes.
// A planes [M][K] row-major; B planes [N][K] (pre-transposed).
// 128x128 CTA tile, BK=32, 256 threads (8 warps as 2x4), warp tile 64x32.
// Smem stride 40 bf16 -> conflict-free LDS.32 fragment loads.
// ---------------------------------------------------------------------------
#define SSTR 40
#define PLSZ (128 * SSTR)            // bf16 units per plane
#define BUFSZ (4 * PLSZ)             // Ahi,Alo,Bhi,Blo
#define GEMM_SMEM (2 * BUFSZ * 2)    // bytes (2 buffers, 2B/elt)

__device__ __forceinline__ void cp16(uint32_t dst, const void* src) {
    asm volatile("cp.async.cg.shared.global [%0], [%1], 16;\n" :: "r"(dst), "l"(src));
}

__device__ __forceinline__ void mma_bf16(float c[4], uint32_t a0, uint32_t a1,
                                         uint32_t a2, uint32_t a3,
                                         uint32_t b0, uint32_t b1) {
    asm volatile(
        "mma.sync.aligned.m16n8k16.row.col.f32.bf16.bf16.f32 "
        "{%0,%1,%2,%3}, {%4,%5,%6,%7}, {%8,%9}, {%0,%1,%2,%3};\n"
        : "+f"(c[0]), "+f"(c[1]), "+f"(c[2]), "+f"(c[3])
        : "r"(a0), "r"(a1), "r"(a2), "r"(a3), "r"(b0), "r"(b1));
}

__device__ __forceinline__ uint32_t lds32(const __nv_bfloat16* p) {
    return *(const uint32_t*)p;
}

__global__ __launch_bounds__(256, 2)
void gemm_bf16x3(const __nv_bfloat16* __restrict__ Ahi,
                 const __nv_bfloat16* __restrict__ Alo,
                 const __nv_bfloat16* __restrict__ Bhi,
                 const __nv_bfloat16* __restrict__ Blo,
                 const float* __restrict__ bias, float* __restrict__ C,
                 int M, int N, int K, float scale, int headmode) {
    extern __shared__ __nv_bfloat16 smb[];

    const int tid = threadIdx.x;
    const int m0 = blockIdx.y * 128, n0 = blockIdx.x * 128;
    const int w = tid >> 5, lane = tid & 31;
    const int gid = lane >> 2, tig = lane & 3;
    const int wm = (w & 1) * 64, wn = (w >> 1) * 32;

    float acc[4][4][4];
#pragma unroll
    for (int i = 0; i < 4; i++)
#pragma unroll
        for (int j = 0; j < 4; j++)
#pragma unroll
            for (int c = 0; c < 4; c++) acc[i][j][c] = 0.0f;

    uint32_t sbase[2];
#pragma unroll
    for (int s = 0; s < 2; s++)
        sbase[s] = (uint32_t)__cvta_generic_to_shared(smb + s * BUFSZ);

    const __nv_bfloat16* gplanes[4] = {Ahi, Alo, Bhi, Blo};

    auto issue_tile = [&](int k0, int s) {
        // 4 planes x 128 rows x 4 chunks(16B) = 2048 chunks; 8/thread
#pragma unroll
        for (int i = 0; i < 8; i++) {
            int lin = tid + 256 * i;
            int plane = lin >> 9;
            int within = lin & 511;
            int row = within >> 2, kc = (within & 3) * 8;
            int grow = (plane < 2 ? m0 : n0) + row;
            const __nv_bfloat16* src = gplanes[plane] + (size_t)grow * K + k0 + kc;
            cp16(sbase[s] + (plane * PLSZ + row * SSTR + kc) * 2, src);
        }
        asm volatile("cp.async.commit_group;\n");
    };

    issue_tile(0, 0);
    int cur = 0;

    for (int k0 = 0; k0 < K; k0 += 32) {
        if (k0 + 32 < K) {
            issue_tile(k0 + 32, cur ^ 1);
            asm volatile("cp.async.wait_group 1;\n");
        } else {
            asm volatile("cp.async.wait_group 0;\n");
        }
        __syncthreads();

        const __nv_bfloat16* Ah = smb + cur * BUFSZ;
        const __nv_bfloat16* Al = Ah + PLSZ;
        const __nv_bfloat16* Bh = Ah + 2 * PLSZ;
        const __nv_bfloat16* Bl = Ah + 3 * PLSZ;

#pragma unroll
        for (int kk = 0; kk < 2; kk++) {
            const int k = kk * 16;
            uint32_t bh[4][2], bl[4][2];
#pragma unroll
            for (int nt = 0; nt < 4; nt++) {
                const int n = wn + nt * 8 + gid;
                bh[nt][0] = lds32(Bh + n * SSTR + k + tig * 2);
                bh[nt][1] = lds32(Bh + n * SSTR + k + tig * 2 + 8);
                bl[nt][0] = lds32(Bl + n * SSTR + k + tig * 2);
                bl[nt][1] = lds32(Bl + n * SSTR + k + tig * 2 + 8);
            }
#pragma unroll
            for (int mt = 0; mt < 4; mt++) {
                const int m = wm + mt * 16 + gid;
                uint32_t ah0 = lds32(Ah + m * SSTR + k + tig * 2);
                uint32_t ah1 = lds32(Ah + (m + 8) * SSTR + k + tig * 2);
                uint32_t ah2 = lds32(Ah + m * SSTR + k + tig * 2 + 8);
                uint32_t ah3 = lds32(Ah + (m + 8) * SSTR + k + tig * 2 + 8);
                uint32_t al0 = lds32(Al + m * SSTR + k + tig * 2);
                uint32_t al1 = lds32(Al + (m + 8) * SSTR + k + tig * 2);
                uint32_t al2 = lds32(Al + m * SSTR + k + tig * 2 + 8);
                uint32_t al3 = lds32(Al + (m + 8) * SSTR + k + tig * 2 + 8);
#pragma unroll
                for (int nt = 0; nt < 4; nt++) {
                    mma_bf16(acc[mt][nt], ah0, ah1, ah2, ah3, bh[nt][0], bh[nt][1]);
                    mma_bf16(acc[mt][nt], ah0, ah1, ah2, ah3, bl[nt][0], bl[nt][1]);
                    mma_bf16(acc[mt][nt], al0, al1, al2, al3, bh[nt][0], bh[nt][1]);
                }
            }
        }
        __syncthreads();
        cur ^= 1;
    }

    // Epilogue
#pragma unroll
    for (int mt = 0; mt < 4; mt++) {
#pragma unroll
        for (int rr = 0; rr < 2; rr++) {
            int m = m0 + wm + mt * 16 + gid + rr * 8;
#pragma unroll
            for (int nt = 0; nt < 4; nt++) {
                int col = n0 + wn + nt * 8 + tig * 2;
                float v0 = (acc[mt][nt][rr * 2 + 0] + bias[col]) * scale;
                float v1 = (acc[mt][nt][rr * 2 + 1] + bias[col + 1]) * scale;
                if (headmode) {
                    int bb = m >> 11, t = m & (Tn - 1);
                    int h = col >> 6, dd = col & 63;
                    float2* dst = (float2*)&C[((((size_t)bb * Hh + h) * Tn + t) << 6) + dd];
                    *dst = make_float2(v0, v1);
                } else {
                    *(float2*)&C[(size_t)m * N + col] = make_float2(v0, v1);
                }
            }
        }
    }
}

// ---------------------------------------------------------------------------
// BD3LM mask predicate
// ---------------------------------------------------------------------------
__device__ __forceinline__ bool can_attend(int q, int kv, int bs) {
    bool x0q = q >= NHALF, x0k = kv >= NHALF;
    int bq = (x0q ? q - NHALF : q) / bs;
    int bk = (x0k ? kv - NHALF : kv) / bs;
    return (bq == bk && x0q == x0k) ||
           (bq > bk && x0k && !x0q) ||
           (bq >= bk && x0k && x0q);
}

// ---------------------------------------------------------------------------
// Fused masked flash attention: 64q x 64k tiles, tile-level skipping.
// ---------------------------------------------------------------------------
#define ATTN_SMEM ((64 * 65 * 3 + 64 * 64) * 4)

__global__ __launch_bounds__(256)
void attn_kernel(const float* __restrict__ Q, const float* __restrict__ K,
                 const float* __restrict__ V, float* __restrict__ C,
                 const int* __restrict__ bs_ptr) {
    extern __shared__ float smA[];
    float* Qs = smA;
    float* Ks = Qs + 64 * 65;
    float* Vs = Ks + 64 * 65;
    float* Ps = Vs + 64 * 64;

    int bs = 4;
    if (bs_ptr) {
        int v = *bs_ptr;
        if (v >= 1 && v <= Tn) bs = v;
    }

    const int tid = threadIdx.x;
    const int qt = gridDim.x - 1 - blockIdx.x;   // heavy tiles first
    const int h = blockIdx.y, b = blockIdx.z;
    const int q0 = qt * 64;
    const size_t base = ((size_t)b * Hh + h) * Tn * HD;

    {
        int r = tid >> 2, cs = (tid & 3) * 16;
        const float* src = Q + base + (size_t)(q0 + r) * HD + cs;
#pragma unroll
        for (int i = 0; i < 4; i++) {
            float4 v4 = *(const float4*)(src + i * 4);
            Qs[r * 65 + cs + i * 4 + 0] = v4.x;
            Qs[r * 65 + cs + i * 4 + 1] = v4.y;
            Qs[r * 65 + cs + i * 4 + 2] = v4.z;
            Qs[r * 65 + cs + i * 4 + 3] = v4.w;
        }
    }

    const int ty = tid >> 4, tx = tid & 15;
    float m_i[4], l_i[4], acc[4][4];
#pragma unroll
    for (int i = 0; i < 4; i++) {
        m_i[i] = -1e30f;
        l_i[i] = 0.0f;
#pragma unroll
        for (int j = 0; j < 4; j++) acc[i][j] = 0.0f;
    }

    const bool x0q = q0 >= NHALF;
    const int bqlo = (x0q ? q0 - NHALF : q0) / bs;
    const int bqhi = (x0q ? q0 + 63 - NHALF : q0 + 63) / bs;

    for (int kt = 0; kt < Tn / 64; kt++) {
        const int k0 = kt * 64;
        {
            bool x0k = k0 >= NHALF;
            int bklo = (x0k ? k0 - NHALF : k0) / bs;
            int bkhi = (x0k ? k0 + 63 - NHALF : k0 + 63) / bs;
            bool any = (x0q == x0k && bqhi >= bklo && bkhi >= bqlo) ||
                       (!x0q && x0k && bqhi > bklo) ||
                       (x0q && x0k && bqhi >= bklo);
            if (!any) continue;
        }
        __syncthreads();
        {
            int r = tid >> 2, cs = (tid & 3) * 16;
            const float* ksrc = K + base + (size_t)(k0 + r) * HD + cs;
            const float* vsrc = V + base + (size_t)(k0 + r) * HD + cs;
#pragma unroll
            for (int i = 0; i < 4; i++) {
                float4 k4 = *(const float4*)(ksrc + i * 4);
                Ks[r * 65 + cs + i * 4 + 0] = k4.x;
                Ks[r * 65 + cs + i * 4 + 1] = k4.y;
                Ks[r * 65 + cs + i * 4 + 2] = k4.z;
                Ks[r * 65 + cs + i * 4 + 3] = k4.w;
                *(float4*)(Vs + r * 64 + cs + i * 4) = *(const float4*)(vsrc + i * 4);
            }
        }
        __syncthreads();

        float s[4][4];
#pragma unroll
        for (int i = 0; i < 4; i++)
#pragma unroll
            for (int j = 0; j < 4; j++) s[i][j] = 0.0f;
#pragma unroll 8
        for (int d = 0; d < 64; d++) {
            float a[4], bb[4];
#pragma unroll
            for (int i = 0; i < 4; i++) a[i] = Qs[(ty * 4 + i) * 65 + d];
#pragma unroll
            for (int j = 0; j < 4; j++) bb[j] = Ks[(tx * 4 + j) * 65 + d];
#pragma unroll
            for (int i = 0; i < 4; i++)
#pragma unroll
                for (int j = 0; j < 4; j++) s[i][j] += a[i] * bb[j];
        }

#pragma unroll
        for (int i = 0; i < 4; i++) {
            int q = q0 + ty * 4 + i;
#pragma unroll
            for (int j = 0; j < 4; j++) {
                int kv = k0 + tx * 4 + j;
                if (!can_attend(q, kv, bs)) s[i][j] = -1e30f;
            }
        }

#pragma unroll
        for (int i = 0; i < 4; i++) {
            float rm = fmaxf(fmaxf(s[i][0], s[i][1]), fmaxf(s[i][2], s[i][3]));
            rm = fmaxf(rm, __shfl_xor_sync(0xffffffffu, rm, 1));
            rm = fmaxf(rm, __shfl_xor_sync(0xffffffffu, rm, 2));
            rm = fmaxf(rm, __shfl_xor_sync(0xffffffffu, rm, 4));
            rm = fmaxf(rm, __shfl_xor_sync(0xffffffffu, rm, 8));
            float mnew = fmaxf(m_i[i], rm);
            float rs = 0.0f;
#pragma unroll
            for (int j = 0; j < 4; j++) {
                s[i][j] = __expf(s[i][j] - mnew);
                rs += s[i][j];
            }
            rs += __shfl_xor_sync(0xffffffffu, rs, 1);
            rs += __shfl_xor_sync(0xffffffffu, rs, 2);
            rs += __shfl_xor_sync(0xffffffffu, rs, 4);
            rs += __shfl_xor_sync(0xffffffffu, rs, 8);
            float f = __expf(m_i[i] - mnew);
            l_i[i] = l_i[i] * f + rs;
            m_i[i] = mnew;
#pragma unroll
            for (int j = 0; j < 4; j++) {
                acc[i][j] *= f;
                Ps[(ty * 4 + i) * 65 + tx * 4 + j] = s[i][j];
            }
        }
        __syncthreads();

#pragma unroll 8
        for (int k = 0; k < 64; k++) {
            float a[4], bb[4];
#pragma unroll
            for (int i = 0; i < 4; i++) a[i] = Ps[(ty * 4 + i) * 65 + k];
#pragma unroll
            for (int j = 0; j < 4; j++) bb[j] = Vs[k * 64 + tx * 4 + j];
#pragma unroll
            for (int i = 0; i < 4; i++)
#pragma unroll
                for (int j = 0; j < 4; j++) acc[i][j] += a[i] * bb[j];
        }
    }

#pragma unroll
    for (int i = 0; i < 4; i++) {
        float inv = 1.0f / l_i[i];
        int t = q0 + ty * 4 + i;
#pragma unroll
        for (int j = 0; j < 4; j++) {
            C[((size_t)b * Tn + t) * Dm + h * HD + tx * 4 + j] = acc[i][j] * inv;
        }
    }
}

// ---------------------------------------------------------------------------
extern "C" void kernel_launch(void* const* d_in, const int* in_sizes, int n_in,
                              void* d_out, int out_size) {
    const float* x  = (const float*)d_in[0];
    const float* Wq = (const float*)d_in[1];
    const float* bq = (const float*)d_in[2];
    const float* Wk = (const float*)d_in[3];
    const float* bk = (const float*)d_in[4];
    const float* Wv = (const float*)d_in[5];
    const float* bv = (const float*)d_in[6];
    const float* Wo = (const float*)d_in[7];
    const float* bo = (const float*)d_in[8];
    const int* bsp  = (n_in > 9) ? (const int*)d_in[9] : nullptr;

    float *qb, *kb, *vb, *cb;
    cudaGetSymbolAddress((void**)&qb, g_Q);
    cudaGetSymbolAddress((void**)&kb, g_K);
    cudaGetSymbolAddress((void**)&vb, g_V);
    cudaGetSymbolAddress((void**)&cb, g_C);

    __nv_bfloat16 *xh, *xl, *ch, *cl;
    __nv_bfloat16 *wqh, *wql, *wkh, *wkl, *wvh, *wvl, *woh, *wol;
    cudaGetSymbolAddress((void**)&xh, g_xhi);
    cudaGetSymbolAddress((void**)&xl, g_xlo);
    cudaGetSymbolAddress((void**)&ch, g_chi);
    cudaGetSymbolAddress((void**)&cl, g_clo);
    cudaGetSymbolAddress((void**)&wqh, g_wqh);
    cudaGetSymbolAddress((void**)&wql, g_wql);
    cudaGetSymbolAddress((void**)&wkh, g_wkh);
    cudaGetSymbolAddress((void**)&wkl, g_wkl);
    cudaGetSymbolAddress((void**)&wvh, g_wvh);
    cudaGetSymbolAddress((void**)&wvl, g_wvl);
    cudaGetSymbolAddress((void**)&woh, g_woh);
    cudaGetSymbolAddress((void**)&wol, g_wol);

    cudaFuncSetAttribute(attn_kernel, cudaFuncAttributeMaxDynamicSharedMemorySize,
                         ATTN_SMEM);
    cudaFuncSetAttribute(gemm_bf16x3, cudaFuncAttributeMaxDynamicSharedMemorySize,
                         GEMM_SMEM);

    const int M = Bz * Tn;
    const int nx4 = Bz * Tn * Dm / 4;

    // Pre-split inputs
    split_rows<<<(nx4 + 255) / 256, 256>>>((const float4*)x, xh, xl, nx4);
    dim3 tg(Dm / 32, Dm / 32), tb(32, 8);
    split_T<<<tg, tb>>>(Wq, wqh, wql);
    split_T<<<tg, tb>>>(Wk, wkh, wkl);
    split_T<<<tg, tb>>>(Wv, wvh, wvl);
    split_T<<<tg, tb>>>(Wo, woh, wol);

    dim3 gg(Dm / 128, M / 128);
    const float qscale = 0.125f;  // hd^-0.5, hd=64

    gemm_bf16x3<<<gg, 256, GEMM_SMEM>>>(xh, xl, wqh, wql, bq, qb, M, Dm, Dm, qscale, 1);
    gemm_bf16x3<<<gg, 256, GEMM_SMEM>>>(xh, xl, wkh, wkl, bk, kb, M, Dm, Dm, 1.0f, 1);
    gemm_bf16x3<<<gg, 256, GEMM_SMEM>>>(xh, xl, wvh, wvl, bv, vb, M, Dm, Dm, 1.0f, 1);

    dim3 ga(Tn / 64, Hh, Bz);
    attn_kernel<<<ga, 256, ATTN_SMEM>>>(qb, kb, vb, cb, bsp);

    split_rows<<<(nx4 + 255) / 256, 256>>>((const float4*)cb, ch, cl, nx4);
    gemm_bf16x3<<<gg, 256, GEMM_SMEM>>>(ch, cl, woh, wol, bo, (float*)d_out,
                                        M, Dm, Dm, 1.0f, 0);
}

// round 8
// speedup vs baseline: 2.3856x; 1.3458x over previous
#include <cuda_runtime.h>
#include <cuda_bf16.h>
#include <math.h>
#include <stdint.h>

#define Bz 4
#define Tn 2048
#define Dm 1024
#define Hh 16
#define HD 64
#define NHALF 1024   // Tn/2

// Scratch (device globals — allocation-free per harness rules)
__device__ float g_C[(size_t)Bz * Tn * Dm];

// Q/K/V bf16 split planes [b,h,t,d]
__device__ __nv_bfloat16 g_Qh[(size_t)Bz * Hh * Tn * HD];
__device__ __nv_bfloat16 g_Ql[(size_t)Bz * Hh * Tn * HD];
__device__ __nv_bfloat16 g_Kh[(size_t)Bz * Hh * Tn * HD];
__device__ __nv_bfloat16 g_Kl[(size_t)Bz * Hh * Tn * HD];
__device__ __nv_bfloat16 g_Vh[(size_t)Bz * Hh * Tn * HD];
__device__ __nv_bfloat16 g_Vl[(size_t)Bz * Hh * Tn * HD];

// x / ctx bf16 split planes
__device__ __nv_bfloat16 g_xhi[(size_t)Bz * Tn * Dm];
__device__ __nv_bfloat16 g_xlo[(size_t)Bz * Tn * Dm];
__device__ __nv_bfloat16 g_chi[(size_t)Bz * Tn * Dm];
__device__ __nv_bfloat16 g_clo[(size_t)Bz * Tn * Dm];
// weights TRANSPOSED [N][K], split planes
__device__ __nv_bfloat16 g_wqh[(size_t)Dm * Dm];
__device__ __nv_bfloat16 g_wql[(size_t)Dm * Dm];
__device__ __nv_bfloat16 g_wkh[(size_t)Dm * Dm];
__device__ __nv_bfloat16 g_wkl[(size_t)Dm * Dm];
__device__ __nv_bfloat16 g_wvh[(size_t)Dm * Dm];
__device__ __nv_bfloat16 g_wvl[(size_t)Dm * Dm];
__device__ __nv_bfloat16 g_woh[(size_t)Dm * Dm];
__device__ __nv_bfloat16 g_wol[(size_t)Dm * Dm];

// ---------------------------------------------------------------------------
__device__ __forceinline__ void bf16_split(float x, __nv_bfloat16& h, __nv_bfloat16& l) {
    h = __float2bfloat16_rn(x);
    l = __float2bfloat16_rn(x - __bfloat162float(h));
}

__global__ __launch_bounds__(256)
void split_rows(const float4* __restrict__ in, __nv_bfloat16* __restrict__ hi,
                __nv_bfloat16* __restrict__ lo, int n4) {
    int i = blockIdx.x * blockDim.x + threadIdx.x;
    if (i >= n4) return;
    float4 v = in[i];
    __nv_bfloat16 h[4], l[4];
    bf16_split(v.x, h[0], l[0]);
    bf16_split(v.y, h[1], l[1]);
    bf16_split(v.z, h[2], l[2]);
    bf16_split(v.w, h[3], l[3]);
    ushort4 hv = make_ushort4(__bfloat16_as_ushort(h[0]), __bfloat16_as_ushort(h[1]),
                              __bfloat16_as_ushort(h[2]), __bfloat16_as_ushort(h[3]));
    ushort4 lv = make_ushort4(__bfloat16_as_ushort(l[0]), __bfloat16_as_ushort(l[1]),
                              __bfloat16_as_ushort(l[2]), __bfloat16_as_ushort(l[3]));
    ((ushort4*)hi)[i] = hv;
    ((ushort4*)lo)[i] = lv;
}

__global__ __launch_bounds__(256)
void split_T(const float* __restrict__ W, __nv_bfloat16* __restrict__ hi,
             __nv_bfloat16* __restrict__ lo) {
    __shared__ float tile[32][33];
    int tx = threadIdx.x, ty = threadIdx.y;
    int nb = blockIdx.x * 32, kb = blockIdx.y * 32;
#pragma unroll
    for (int j = 0; j < 32; j += 8)
        tile[ty + j][tx] = W[(size_t)(kb + ty + j) * Dm + nb + tx];
    __syncthreads();
#pragma unroll
    for (int j = 0; j < 32; j += 8) {
        int n = nb + ty + j, k = kb + tx;
        __nv_bfloat16 h, l;
        bf16_split(tile[tx][ty + j], h, l);
        hi[(size_t)n * Dm + k] = h;
        lo[(size_t)n * Dm + k] = l;
    }
}

// ---------------------------------------------------------------------------
// 3x-bf16 GEMM. headmode=1: write bf16 split planes [b,h,t,d]; 0: fp32 [M,N].
// ---------------------------------------------------------------------------
#define SSTR 40
#define PLSZ (128 * SSTR)
#define BUFSZ (4 * PLSZ)
#define GEMM_SMEM (2 * BUFSZ * 2)

__device__ __forceinline__ void cp16(uint32_t dst, const void* src) {
    asm volatile("cp.async.cg.shared.global [%0], [%1], 16;\n" :: "r"(dst), "l"(src));
}

__device__ __forceinline__ void mma_bf16(float c[4], uint32_t a0, uint32_t a1,
                                         uint32_t a2, uint32_t a3,
                                         uint32_t b0, uint32_t b1) {
    asm volatile(
        "mma.sync.aligned.m16n8k16.row.col.f32.bf16.bf16.f32 "
        "{%0,%1,%2,%3}, {%4,%5,%6,%7}, {%8,%9}, {%0,%1,%2,%3};\n"
        : "+f"(c[0]), "+f"(c[1]), "+f"(c[2]), "+f"(c[3])
        : "r"(a0), "r"(a1), "r"(a2), "r"(a3), "r"(b0), "r"(b1));
}

__device__ __forceinline__ uint32_t lds32(const __nv_bfloat16* p) {
    return *(const uint32_t*)p;
}

__global__ __launch_bounds__(256, 2)
void gemm_bf16x3(const __nv_bfloat16* __restrict__ Ahi,
                 const __nv_bfloat16* __restrict__ Alo,
                 const __nv_bfloat16* __restrict__ Bhi,
                 const __nv_bfloat16* __restrict__ Blo,
                 const float* __restrict__ bias, float* __restrict__ C,
                 __nv_bfloat16* __restrict__ Phi, __nv_bfloat16* __restrict__ Plo,
                 int M, int N, int K, float scale, int headmode) {
    extern __shared__ __nv_bfloat16 smb[];

    const int tid = threadIdx.x;
    const int m0 = blockIdx.y * 128, n0 = blockIdx.x * 128;
    const int w = tid >> 5, lane = tid & 31;
    const int gid = lane >> 2, tig = lane & 3;
    const int wm = (w & 1) * 64, wn = (w >> 1) * 32;

    float acc[4][4][4];
#pragma unroll
    for (int i = 0; i < 4; i++)
#pragma unroll
        for (int j = 0; j < 4; j++)
#pragma unroll
            for (int c = 0; c < 4; c++) acc[i][j][c] = 0.0f;

    uint32_t sbase[2];
#pragma unroll
    for (int s = 0; s < 2; s++)
        sbase[s] = (uint32_t)__cvta_generic_to_shared(smb + s * BUFSZ);

    const __nv_bfloat16* gplanes[4] = {Ahi, Alo, Bhi, Blo};

    auto issue_tile = [&](int k0, int s) {
#pragma unroll
        for (int i = 0; i < 8; i++) {
            int lin = tid + 256 * i;
            int plane = lin >> 9;
            int within = lin & 511;
            int row = within >> 2, kc = (within & 3) * 8;
            int grow = (plane < 2 ? m0 : n0) + row;
            cp16(sbase[s] + (plane * PLSZ + row * SSTR + kc) * 2,
                 gplanes[plane] + (size_t)grow * K + k0 + kc);
        }
        asm volatile("cp.async.commit_group;\n");
    };

    issue_tile(0, 0);
    int cur = 0;

    for (int k0 = 0; k0 < K; k0 += 32) {
        if (k0 + 32 < K) {
            issue_tile(k0 + 32, cur ^ 1);
            asm volatile("cp.async.wait_group 1;\n");
        } else {
            asm volatile("cp.async.wait_group 0;\n");
        }
        __syncthreads();

        const __nv_bfloat16* Ah = smb + cur * BUFSZ;
        const __nv_bfloat16* Al = Ah + PLSZ;
        const __nv_bfloat16* Bh = Ah + 2 * PLSZ;
        const __nv_bfloat16* Bl = Ah + 3 * PLSZ;

#pragma unroll
        for (int kk = 0; kk < 2; kk++) {
            const int k = kk * 16;
            uint32_t bh[4][2], bl[4][2];
#pragma unroll
            for (int nt = 0; nt < 4; nt++) {
                const int n = wn + nt * 8 + gid;
                bh[nt][0] = lds32(Bh + n * SSTR + k + tig * 2);
                bh[nt][1] = lds32(Bh + n * SSTR + k + tig * 2 + 8);
                bl[nt][0] = lds32(Bl + n * SSTR + k + tig * 2);
                bl[nt][1] = lds32(Bl + n * SSTR + k + tig * 2 + 8);
            }
#pragma unroll
            for (int mt = 0; mt < 4; mt++) {
                const int m = wm + mt * 16 + gid;
                uint32_t ah0 = lds32(Ah + m * SSTR + k + tig * 2);
                uint32_t ah1 = lds32(Ah + (m + 8) * SSTR + k + tig * 2);
                uint32_t ah2 = lds32(Ah + m * SSTR + k + tig * 2 + 8);
                uint32_t ah3 = lds32(Ah + (m + 8) * SSTR + k + tig * 2 + 8);
                uint32_t al0 = lds32(Al + m * SSTR + k + tig * 2);
                uint32_t al1 = lds32(Al + (m + 8) * SSTR + k + tig * 2);
                uint32_t al2 = lds32(Al + m * SSTR + k + tig * 2 + 8);
                uint32_t al3 = lds32(Al + (m + 8) * SSTR + k + tig * 2 + 8);
#pragma unroll
                for (int nt = 0; nt < 4; nt++) {
                    mma_bf16(acc[mt][nt], ah0, ah1, ah2, ah3, bh[nt][0], bh[nt][1]);
                    mma_bf16(acc[mt][nt], ah0, ah1, ah2, ah3, bl[nt][0], bl[nt][1]);
                    mma_bf16(acc[mt][nt], al0, al1, al2, al3, bh[nt][0], bh[nt][1]);
                }
            }
        }
        __syncthreads();
        cur ^= 1;
    }

#pragma unroll
    for (int mt = 0; mt < 4; mt++) {
#pragma unroll
        for (int rr = 0; rr < 2; rr++) {
            int m = m0 + wm + mt * 16 + gid + rr * 8;
#pragma unroll
            for (int nt = 0; nt < 4; nt++) {
                int col = n0 + wn + nt * 8 + tig * 2;
                float v0 = (acc[mt][nt][rr * 2 + 0] + bias[col]) * scale;
                float v1 = (acc[mt][nt][rr * 2 + 1] + bias[col + 1]) * scale;
                if (headmode) {
                    int bb = m >> 11, t = m & (Tn - 1);
                    int hh = col >> 6, dd = col & 63;
                    size_t idx = ((((size_t)bb * Hh + hh) * Tn + t) << 6) + dd;
                    __nv_bfloat16 h0, l0, h1, l1;
                    bf16_split(v0, h0, l0);
                    bf16_split(v1, h1, l1);
                    *(ushort2*)&Phi[idx] = make_ushort2(__bfloat16_as_ushort(h0),
                                                        __bfloat16_as_ushort(h1));
                    *(ushort2*)&Plo[idx] = make_ushort2(__bfloat16_as_ushort(l0),
                                                        __bfloat16_as_ushort(l1));
                } else {
                    *(float2*)&C[(size_t)m * N + col] = make_float2(v0, v1);
                }
            }
        }
    }
}

// ---------------------------------------------------------------------------
// Tensor-core masked flash attention (double-bf16).
// 128 threads / 4 warps; warp = 16 q rows; 64q x 64k tiles; tile skipping.
// ---------------------------------------------------------------------------
#define AST 72   // bf16 row stride in attn smem (36 words)

__global__ __launch_bounds__(128)
void attn_mma(const __nv_bfloat16* __restrict__ Qh, const __nv_bfloat16* __restrict__ Ql,
              const __nv_bfloat16* __restrict__ Kh, const __nv_bfloat16* __restrict__ Kl,
              const __nv_bfloat16* __restrict__ Vh, const __nv_bfloat16* __restrict__ Vl,
              float* __restrict__ C, const int* __restrict__ bs_ptr) {
    __shared__ __nv_bfloat16 sK[2][64 * AST];    // [plane][kv][d]
    __shared__ __nv_bfloat16 sVT[2][64 * AST];   // [plane][d][kv]

    int bs = 4;
    if (bs_ptr) {
        int v = *bs_ptr;
        if (v >= 1 && v <= Tn) bs = v;
    }

    const int tid = threadIdx.x, w = tid >> 5, lane = tid & 31;
    const int gid = lane >> 2, tig = lane & 3;
    const int qt = gridDim.x - 1 - blockIdx.x;   // heavy tiles first
    const int h = blockIdx.y, b = blockIdx.z;
    const int q0 = qt * 64;
    const size_t base = ((size_t)b * Hh + h) * Tn * HD;

    // Q fragments (hoisted): rows r0, r0+8; 4 k-chunks, hi+lo
    const int r0 = q0 + w * 16 + gid;
    uint32_t qfh[4][4], qfl[4][4];
#pragma unroll
    for (int kc = 0; kc < 4; kc++) {
        const size_t o = base + (size_t)r0 * HD + kc * 16 + tig * 2;
        qfh[kc][0] = *(const uint32_t*)(Qh + o);
        qfh[kc][1] = *(const uint32_t*)(Qh + o + 8 * HD);
        qfh[kc][2] = *(const uint32_t*)(Qh + o + 8);
        qfh[kc][3] = *(const uint32_t*)(Qh + o + 8 * HD + 8);
        qfl[kc][0] = *(const uint32_t*)(Ql + o);
        qfl[kc][1] = *(const uint32_t*)(Ql + o + 8 * HD);
        qfl[kc][2] = *(const uint32_t*)(Ql + o + 8);
        qfl[kc][3] = *(const uint32_t*)(Ql + o + 8 * HD + 8);
    }

    const bool x0q = (r0 >= NHALF);
    const int bq0 = (x0q ? r0 - NHALF : r0) / bs;
    const int bq1 = (x0q ? r0 + 8 - NHALF : r0 + 8) / bs;

    float cac[8][4];
#pragma unroll
    for (int i = 0; i < 8; i++)
#pragma unroll
        for (int j = 0; j < 4; j++) cac[i][j] = 0.0f;
    float mi0 = -1e30f, mi1 = -1e30f, li0 = 0.0f, li1 = 0.0f;

    const int bqlo = (x0q ? q0 - NHALF : q0) / bs;
    const int bqhi = (x0q ? q0 + 63 - NHALF : q0 + 63) / bs;

    for (int kt = 0; kt < Tn / 64; kt++) {
        const int k0 = kt * 64;
        const bool x0k = (k0 >= NHALF);
        {
            int bklo = (x0k ? k0 - NHALF : k0) / bs;
            int bkhi = (x0k ? k0 + 63 - NHALF : k0 + 63) / bs;
            bool any = (x0q == x0k && bqhi >= bklo && bkhi >= bqlo) ||
                       (!x0q && x0k && bqhi > bklo) ||
                       (x0q && x0k && bqhi >= bklo);
            if (!any) continue;
        }
        __syncthreads();
        // Load K planes (direct) and V planes (transposed)
        {
            const __nv_bfloat16* kp[2] = {Kh + base + (size_t)k0 * HD,
                                          Kl + base + (size_t)k0 * HD};
            const __nv_bfloat16* vp[2] = {Vh + base + (size_t)k0 * HD,
                                          Vl + base + (size_t)k0 * HD};
#pragma unroll
            for (int p = 0; p < 2; p++) {
#pragma unroll
                for (int i = 0; i < 8; i++) {
                    int lin = tid + 128 * i;
                    int row = lin >> 4, c4 = (lin & 15) * 4;
                    *(uint2*)(sK[p] + row * AST + c4) =
                        *(const uint2*)(kp[p] + row * HD + c4);
                    ushort4 vv = *(const ushort4*)(vp[p] + row * HD + c4);
                    unsigned short* vt = (unsigned short*)sVT[p];
                    vt[(c4 + 0) * AST + row] = vv.x;
                    vt[(c4 + 1) * AST + row] = vv.y;
                    vt[(c4 + 2) * AST + row] = vv.z;
                    vt[(c4 + 3) * AST + row] = vv.w;
                }
            }
        }
        __syncthreads();

        // S = Q K^T (3-mma double-bf16)
        float sac[8][4];
#pragma unroll
        for (int i = 0; i < 8; i++)
#pragma unroll
            for (int j = 0; j < 4; j++) sac[i][j] = 0.0f;
#pragma unroll
        for (int kc = 0; kc < 4; kc++) {
#pragma unroll
            for (int nt = 0; nt < 8; nt++) {
                const __nv_bfloat16* kh = sK[0] + (nt * 8 + gid) * AST + kc * 16 + tig * 2;
                const __nv_bfloat16* kl = sK[1] + (nt * 8 + gid) * AST + kc * 16 + tig * 2;
                uint32_t bh0 = lds32(kh), bh1 = lds32(kh + 8);
                uint32_t bl0 = lds32(kl), bl1 = lds32(kl + 8);
                mma_bf16(sac[nt], qfh[kc][0], qfh[kc][1], qfh[kc][2], qfh[kc][3], bh0, bh1);
                mma_bf16(sac[nt], qfh[kc][0], qfh[kc][1], qfh[kc][2], qfh[kc][3], bl0, bl1);
                mma_bf16(sac[nt], qfl[kc][0], qfl[kc][1], qfl[kc][2], qfl[kc][3], bh0, bh1);
            }
        }

        // Mask
#pragma unroll
        for (int nt = 0; nt < 8; nt++) {
#pragma unroll
            for (int e = 0; e < 2; e++) {
                int col = k0 + nt * 8 + tig * 2 + e;
                int bk = (x0k ? col - NHALF : col) / bs;
                bool c0 = (bq0 == bk && x0q == x0k) || (bq0 > bk && x0k && !x0q) ||
                          (bq0 >= bk && x0k && x0q);
                bool c1 = (bq1 == bk && x0q == x0k) || (bq1 > bk && x0k && !x0q) ||
                          (bq1 >= bk && x0k && x0q);
                if (!c0) sac[nt][e] = -1e30f;
                if (!c1) sac[nt][2 + e] = -1e30f;
            }
        }

        // Online softmax
        float rm0 = -1e30f, rm1 = -1e30f;
#pragma unroll
        for (int nt = 0; nt < 8; nt++) {
            rm0 = fmaxf(rm0, fmaxf(sac[nt][0], sac[nt][1]));
            rm1 = fmaxf(rm1, fmaxf(sac[nt][2], sac[nt][3]));
        }
        rm0 = fmaxf(rm0, __shfl_xor_sync(0xffffffffu, rm0, 1));
        rm0 = fmaxf(rm0, __shfl_xor_sync(0xffffffffu, rm0, 2));
        rm1 = fmaxf(rm1, __shfl_xor_sync(0xffffffffu, rm1, 1));
        rm1 = fmaxf(rm1, __shfl_xor_sync(0xffffffffu, rm1, 2));
        float mn0 = fmaxf(mi0, rm0), mn1 = fmaxf(mi1, rm1);
        float f0 = __expf(mi0 - mn0), f1 = __expf(mi1 - mn1);
        mi0 = mn0; mi1 = mn1;
        float rs0 = 0.0f, rs1 = 0.0f;
#pragma unroll
        for (int nt = 0; nt < 8; nt++) {
            sac[nt][0] = __expf(sac[nt][0] - mn0);
            sac[nt][1] = __expf(sac[nt][1] - mn0);
            sac[nt][2] = __expf(sac[nt][2] - mn1);
            sac[nt][3] = __expf(sac[nt][3] - mn1);
            rs0 += sac[nt][0] + sac[nt][1];
            rs1 += sac[nt][2] + sac[nt][3];
        }
        rs0 += __shfl_xor_sync(0xffffffffu, rs0, 1);
        rs0 += __shfl_xor_sync(0xffffffffu, rs0, 2);
        rs1 += __shfl_xor_sync(0xffffffffu, rs1, 1);
        rs1 += __shfl_xor_sync(0xffffffffu, rs1, 2);
        li0 = li0 * f0 + rs0;
        li1 = li1 * f1 + rs1;
#pragma unroll
        for (int nd = 0; nd < 8; nd++) {
            cac[nd][0] *= f0; cac[nd][1] *= f0;
            cac[nd][2] *= f1; cac[nd][3] *= f1;
        }

        // P repack (reg->reg) + PV (3-mma double-bf16)
#pragma unroll
        for (int kc = 0; kc < 4; kc++) {
            const int nA = kc * 2, nB = kc * 2 + 1;
            uint32_t ph[4], pl[4];
            {
                __nv_bfloat16 hx, lx, hy, ly;
                bf16_split(sac[nA][0], hx, lx); bf16_split(sac[nA][1], hy, ly);
                ph[0] = (uint32_t)__bfloat16_as_ushort(hx) |
                        ((uint32_t)__bfloat16_as_ushort(hy) << 16);
                pl[0] = (uint32_t)__bfloat16_as_ushort(lx) |
                        ((uint32_t)__bfloat16_as_ushort(ly) << 16);
                bf16_split(sac[nA][2], hx, lx); bf16_split(sac[nA][3], hy, ly);
                ph[1] = (uint32_t)__bfloat16_as_ushort(hx) |
                        ((uint32_t)__bfloat16_as_ushort(hy) << 16);
                pl[1] = (uint32_t)__bfloat16_as_ushort(lx) |
                        ((uint32_t)__bfloat16_as_ushort(ly) << 16);
                bf16_split(sac[nB][0], hx, lx); bf16_split(sac[nB][1], hy, ly);
                ph[2] = (uint32_t)__bfloat16_as_ushort(hx) |
                        ((uint32_t)__bfloat16_as_ushort(hy) << 16);
                pl[2] = (uint32_t)__bfloat16_as_ushort(lx) |
                        ((uint32_t)__bfloat16_as_ushort(ly) << 16);
                bf16_split(sac[nB][2], hx, lx); bf16_split(sac[nB][3], hy, ly);
                ph[3] = (uint32_t)__bfloat16_as_ushort(hx) |
                        ((uint32_t)__bfloat16_as_ushort(hy) << 16);
                pl[3] = (uint32_t)__bfloat16_as_ushort(lx) |
                        ((uint32_t)__bfloat16_as_ushort(ly) << 16);
            }
#pragma unroll
            for (int nd = 0; nd < 8; nd++) {
                const __nv_bfloat16* vh = sVT[0] + (nd * 8 + gid) * AST + kc * 16 + tig * 2;
                const __nv_bfloat16* vl = sVT[1] + (nd * 8 + gid) * AST + kc * 16 + tig * 2;
                uint32_t bh0 = lds32(vh), bh1 = lds32(vh + 8);
                uint32_t bl0 = lds32(vl), bl1 = lds32(vl + 8);
                mma_bf16(cac[nd], ph[0], ph[1], ph[2], ph[3], bh0, bh1);
                mma_bf16(cac[nd], ph[0], ph[1], ph[2], ph[3], bl0, bl1);
                mma_bf16(cac[nd], pl[0], pl[1], pl[2], pl[3], bh0, bh1);
            }
        }
    }

    // Epilogue: C[b][t][h*64+d]
    float il0 = 1.0f / li0, il1 = 1.0f / li1;
#pragma unroll
    for (int nd = 0; nd < 8; nd++) {
        int d = h * HD + nd * 8 + tig * 2;
        *(float2*)&C[((size_t)b * Tn + r0) * Dm + d] =
            make_float2(cac[nd][0] * il0, cac[nd][1] * il0);
        *(float2*)&C[((size_t)b * Tn + r0 + 8) * Dm + d] =
            make_float2(cac[nd][2] * il1, cac[nd][3] * il1);
    }
}

// ---------------------------------------------------------------------------
extern "C" void kernel_launch(void* const* d_in, const int* in_sizes, int n_in,
                              void* d_out, int out_size) {
    const float* x  = (const float*)d_in[0];
    const float* Wq = (const float*)d_in[1];
    const float* bq = (const float*)d_in[2];
    const float* Wk = (const float*)d_in[3];
    const float* bk = (const float*)d_in[4];
    const float* Wv = (const float*)d_in[5];
    const float* bv = (const float*)d_in[6];
    const float* Wo = (const float*)d_in[7];
    const float* bo = (const float*)d_in[8];
    const int* bsp  = (n_in > 9) ? (const int*)d_in[9] : nullptr;

    float* cb;
    cudaGetSymbolAddress((void**)&cb, g_C);
    __nv_bfloat16 *qh, *ql, *kh, *kl, *vh, *vl;
    cudaGetSymbolAddress((void**)&qh, g_Qh);
    cudaGetSymbolAddress((void**)&ql, g_Ql);
    cudaGetSymbolAddress((void**)&kh, g_Kh);
    cudaGetSymbolAddress((void**)&kl, g_Kl);
    cudaGetSymbolAddress((void**)&vh, g_Vh);
    cudaGetSymbolAddress((void**)&vl, g_Vl);

    __nv_bfloat16 *xh, *xl, *ch, *cl;
    __nv_bfloat16 *wqh, *wql, *wkh, *wkl, *wvh, *wvl, *woh, *wol;
    cudaGetSymbolAddress((void**)&xh, g_xhi);
    cudaGetSymbolAddress((void**)&xl, g_xlo);
    cudaGetSymbolAddress((void**)&ch, g_chi);
    cudaGetSymbolAddress((void**)&cl, g_clo);
    cudaGetSymbolAddress((void**)&wqh, g_wqh);
    cudaGetSymbolAddress((void**)&wql, g_wql);
    cudaGetSymbolAddress((void**)&wkh, g_wkh);
    cudaGetSymbolAddress((void**)&wkl, g_wkl);
    cudaGetSymbolAddress((void**)&wvh, g_wvh);
    cudaGetSymbolAddress((void**)&wvl, g_wvl);
    cudaGetSymbolAddress((void**)&woh, g_woh);
    cudaGetSymbolAddress((void**)&wol, g_wol);

    cudaFuncSetAttribute(gemm_bf16x3, cudaFuncAttributeMaxDynamicSharedMemorySize,
                         GEMM_SMEM);

    const int M = Bz * Tn;
    const int nx4 = Bz * Tn * Dm / 4;

    split_rows<<<(nx4 + 255) / 256, 256>>>((const float4*)x, xh, xl, nx4);
    dim3 tg(Dm / 32, Dm / 32), tb(32, 8);
    split_T<<<tg, tb>>>(Wq, wqh, wql);
    split_T<<<tg, tb>>>(Wk, wkh, wkl);
    split_T<<<tg, tb>>>(Wv, wvh, wvl);
    split_T<<<tg, tb>>>(Wo, woh, wol);

    dim3 gg(Dm / 128, M / 128);
    const float qscale = 0.125f;  // hd^-0.5, hd=64

    gemm_bf16x3<<<gg, 256, GEMM_SMEM>>>(xh, xl, wqh, wql, bq, nullptr, qh, ql,
                                        M, Dm, Dm, qscale, 1);
    gemm_bf16x3<<<gg, 256, GEMM_SMEM>>>(xh, xl, wkh, wkl, bk, nullptr, kh, kl,
                                        M, Dm, Dm, 1.0f, 1);
    gemm_bf16x3<<<gg, 256, GEMM_SMEM>>>(xh, xl, wvh, wvl, bv, nullptr, vh, vl,
                                        M, Dm, Dm, 1.0f, 1);

    dim3 ga(Tn / 64, Hh, Bz);
    attn_mma<<<ga, 128>>>(qh, ql, kh, kl, vh, vl, cb, bsp);

    split_rows<<<(nx4 + 255) / 256, 256>>>((const float4*)cb, ch, cl, nx4);
    gemm_bf16x3<<<gg, 256, GEMM_SMEM>>>(ch, cl, woh, wol, bo, (float*)d_out,
                                        nullptr, nullptr, M, Dm, Dm, 1.0f, 0);
}

// round 10
// speedup vs baseline: 2.6220x; 1.0991x over previous
#include <cuda_runtime.h>
#include <cuda_bf16.h>
#include <math.h>
#include <stdint.h>

#define Bz 4
#define Tn 2048
#define Dm 1024
#define Hh 16
#define HD 64
#define NHALF 1024   // Tn/2

// Scratch (device globals — allocation-free per harness rules)
__device__ float g_C[(size_t)Bz * Tn * Dm];

// Q/K/V bf16 split planes [b,h,t,d]
__device__ __nv_bfloat16 g_Qh[(size_t)Bz * Hh * Tn * HD];
__device__ __nv_bfloat16 g_Ql[(size_t)Bz * Hh * Tn * HD];
__device__ __nv_bfloat16 g_Kh[(size_t)Bz * Hh * Tn * HD];
__device__ __nv_bfloat16 g_Kl[(size_t)Bz * Hh * Tn * HD];
__device__ __nv_bfloat16 g_Vh[(size_t)Bz * Hh * Tn * HD];
__device__ __nv_bfloat16 g_Vl[(size_t)Bz * Hh * Tn * HD];

// x / ctx bf16 split planes
__device__ __nv_bfloat16 g_xhi[(size_t)Bz * Tn * Dm];
__device__ __nv_bfloat16 g_xlo[(size_t)Bz * Tn * Dm];
__device__ __nv_bfloat16 g_chi[(size_t)Bz * Tn * Dm];
__device__ __nv_bfloat16 g_clo[(size_t)Bz * Tn * Dm];
// weights TRANSPOSED [N][K], split planes
__device__ __nv_bfloat16 g_wqh[(size_t)Dm * Dm];
__device__ __nv_bfloat16 g_wql[(size_t)Dm * Dm];
__device__ __nv_bfloat16 g_wkh[(size_t)Dm * Dm];
__device__ __nv_bfloat16 g_wkl[(size_t)Dm * Dm];
__device__ __nv_bfloat16 g_wvh[(size_t)Dm * Dm];
__device__ __nv_bfloat16 g_wvl[(size_t)Dm * Dm];
__device__ __nv_bfloat16 g_woh[(size_t)Dm * Dm];
__device__ __nv_bfloat16 g_wol[(size_t)Dm * Dm];

// ---------------------------------------------------------------------------
__device__ __forceinline__ void bf16_split(float x, __nv_bfloat16& h, __nv_bfloat16& l) {
    h = __float2bfloat16_rn(x);
    l = __float2bfloat16_rn(x - __bfloat162float(h));
}

__global__ __launch_bounds__(256)
void split_rows(const float4* __restrict__ in, __nv_bfloat16* __restrict__ hi,
                __nv_bfloat16* __restrict__ lo, int n4) {
    int i = blockIdx.x * blockDim.x + threadIdx.x;
    if (i >= n4) return;
    float4 v = in[i];
    __nv_bfloat16 h[4], l[4];
    bf16_split(v.x, h[0], l[0]);
    bf16_split(v.y, h[1], l[1]);
    bf16_split(v.z, h[2], l[2]);
    bf16_split(v.w, h[3], l[3]);
    ushort4 hv = make_ushort4(__bfloat16_as_ushort(h[0]), __bfloat16_as_ushort(h[1]),
                              __bfloat16_as_ushort(h[2]), __bfloat16_as_ushort(h[3]));
    ushort4 lv = make_ushort4(__bfloat16_as_ushort(l[0]), __bfloat16_as_ushort(l[1]),
                              __bfloat16_as_ushort(l[2]), __bfloat16_as_ushort(l[3]));
    ((ushort4*)hi)[i] = hv;
    ((ushort4*)lo)[i] = lv;
}

__global__ __launch_bounds__(256)
void split_T(const float* __restrict__ W, __nv_bfloat16* __restrict__ hi,
             __nv_bfloat16* __restrict__ lo) {
    __shared__ float tile[32][33];
    int tx = threadIdx.x, ty = threadIdx.y;
    int nb = blockIdx.x * 32, kb = blockIdx.y * 32;
#pragma unroll
    for (int j = 0; j < 32; j += 8)
        tile[ty + j][tx] = W[(size_t)(kb + ty + j) * Dm + nb + tx];
    __syncthreads();
#pragma unroll
    for (int j = 0; j < 32; j += 8) {
        int n = nb + ty + j, k = kb + tx;
        __nv_bfloat16 h, l;
        bf16_split(tile[tx][ty + j], h, l);
        hi[(size_t)n * Dm + k] = h;
        lo[(size_t)n * Dm + k] = l;
    }
}

// ---------------------------------------------------------------------------
// Shared low-level helpers
// ---------------------------------------------------------------------------
__device__ __forceinline__ uint32_t smem_u32(const void* p) {
    uint32_t a;
    asm("{ .reg .u64 t; cvta.to.shared.u64 t, %1; cvt.u32.u64 %0, t; }"
        : "=r"(a) : "l"(p));
    return a;
}

__device__ __forceinline__ void cp16(uint32_t dst, const void* src) {
    asm volatile("cp.async.cg.shared.global [%0], [%1], 16;\n" :: "r"(dst), "l"(src));
}

__device__ __forceinline__ void mma_bf16(float c[4], uint32_t a0, uint32_t a1,
                                         uint32_t a2, uint32_t a3,
                                         uint32_t b0, uint32_t b1) {
    asm volatile(
        "mma.sync.aligned.m16n8k16.row.col.f32.bf16.bf16.f32 "
        "{%0,%1,%2,%3}, {%4,%5,%6,%7}, {%8,%9}, {%0,%1,%2,%3};\n"
        : "+f"(c[0]), "+f"(c[1]), "+f"(c[2]), "+f"(c[3])
        : "r"(a0), "r"(a1), "r"(a2), "r"(a3), "r"(b0), "r"(b1));
}

__device__ __forceinline__ uint32_t lds32(const __nv_bfloat16* p) {
    return *(const uint32_t*)p;
}

__device__ __forceinline__ void ldsm_x2(uint32_t& r0, uint32_t& r1, uint32_t addr) {
    asm volatile("ldmatrix.sync.aligned.m8n8.x2.shared.b16 {%0,%1}, [%2];"
                 : "=r"(r0), "=r"(r1) : "r"(addr));
}
__device__ __forceinline__ void ldsm_x2_t(uint32_t& r0, uint32_t& r1, uint32_t addr) {
    asm volatile("ldmatrix.sync.aligned.m8n8.x2.trans.shared.b16 {%0,%1}, [%2];"
                 : "=r"(r0), "=r"(r1) : "r"(addr));
}

// ---------------------------------------------------------------------------
// 3x-bf16 GEMM (R8, proven). headmode=1: bf16 split planes [b,h,t,d]; 0: fp32.
// ---------------------------------------------------------------------------
#define SSTR 40
#define PLSZ (128 * SSTR)
#define BUFSZ (4 * PLSZ)
#define GEMM_SMEM (2 * BUFSZ * 2)

__global__ __launch_bounds__(256, 2)
void gemm_bf16x3(const __nv_bfloat16* __restrict__ Ahi,
                 const __nv_bfloat16* __restrict__ Alo,
                 const __nv_bfloat16* __restrict__ Bhi,
                 const __nv_bfloat16* __restrict__ Blo,
                 const float* __restrict__ bias, float* __restrict__ C,
                 __nv_bfloat16* __restrict__ Phi, __nv_bfloat16* __restrict__ Plo,
                 int M, int N, int K, float scale, int headmode) {
    extern __shared__ __nv_bfloat16 smb[];

    const int tid = threadIdx.x;
    const int m0 = blockIdx.y * 128, n0 = blockIdx.x * 128;
    const int w = tid >> 5, lane = tid & 31;
    const int gid = lane >> 2, tig = lane & 3;
    const int wm = (w & 1) * 64, wn = (w >> 1) * 32;

    float acc[4][4][4];
#pragma unroll
    for (int i = 0; i < 4; i++)
#pragma unroll
        for (int j = 0; j < 4; j++)
#pragma unroll
            for (int c = 0; c < 4; c++) acc[i][j][c] = 0.0f;

    uint32_t sbase[2];
#pragma unroll
    for (int s = 0; s < 2; s++)
        sbase[s] = (uint32_t)__cvta_generic_to_shared(smb + s * BUFSZ);

    const __nv_bfloat16* gplanes[4] = {Ahi, Alo, Bhi, Blo};

    auto issue_tile = [&](int k0, int s) {
#pragma unroll
        for (int i = 0; i < 8; i++) {
            int lin = tid + 256 * i;
            int plane = lin >> 9;
            int within = lin & 511;
            int row = within >> 2, kc = (within & 3) * 8;
            int grow = (plane < 2 ? m0 : n0) + row;
            cp16(sbase[s] + (plane * PLSZ + row * SSTR + kc) * 2,
                 gplanes[plane] + (size_t)grow * K + k0 + kc);
        }
        asm volatile("cp.async.commit_group;\n");
    };

    issue_tile(0, 0);
    int cur = 0;

    for (int k0 = 0; k0 < K; k0 += 32) {
        if (k0 + 32 < K) {
            issue_tile(k0 + 32, cur ^ 1);
            asm volatile("cp.async.wait_group 1;\n");
        } else {
            asm volatile("cp.async.wait_group 0;\n");
        }
        __syncthreads();

        const __nv_bfloat16* Ah = smb + cur * BUFSZ;
        const __nv_bfloat16* Al = Ah + PLSZ;
        const __nv_bfloat16* Bh = Ah + 2 * PLSZ;
        const __nv_bfloat16* Bl = Ah + 3 * PLSZ;

#pragma unroll
        for (int kk = 0; kk < 2; kk++) {
            const int k = kk * 16;
            uint32_t bh[4][2], bl[4][2];
#pragma unroll
            for (int nt = 0; nt < 4; nt++) {
                const int n = wn + nt * 8 + gid;
                bh[nt][0] = lds32(Bh + n * SSTR + k + tig * 2);
                bh[nt][1] = lds32(Bh + n * SSTR + k + tig * 2 + 8);
                bl[nt][0] = lds32(Bl + n * SSTR + k + tig * 2);
                bl[nt][1] = lds32(Bl + n * SSTR + k + tig * 2 + 8);
            }
#pragma unroll
            for (int mt = 0; mt < 4; mt++) {
                const int m = wm + mt * 16 + gid;
                uint32_t ah0 = lds32(Ah + m * SSTR + k + tig * 2);
                uint32_t ah1 = lds32(Ah + (m + 8) * SSTR + k + tig * 2);
                uint32_t ah2 = lds32(Ah + m * SSTR + k + tig * 2 + 8);
                uint32_t ah3 = lds32(Ah + (m + 8) * SSTR + k + tig * 2 + 8);
                uint32_t al0 = lds32(Al + m * SSTR + k + tig * 2);
                uint32_t al1 = lds32(Al + (m + 8) * SSTR + k + tig * 2);
                uint32_t al2 = lds32(Al + m * SSTR + k + tig * 2 + 8);
                uint32_t al3 = lds32(Al + (m + 8) * SSTR + k + tig * 2 + 8);
#pragma unroll
                for (int nt = 0; nt < 4; nt++) {
                    mma_bf16(acc[mt][nt], ah0, ah1, ah2, ah3, bh[nt][0], bh[nt][1]);
                    mma_bf16(acc[mt][nt], ah0, ah1, ah2, ah3, bl[nt][0], bl[nt][1]);
                    mma_bf16(acc[mt][nt], al0, al1, al2, al3, bh[nt][0], bh[nt][1]);
                }
            }
        }
        __syncthreads();
        cur ^= 1;
    }

#pragma unroll
    for (int mt = 0; mt < 4; mt++) {
#pragma unroll
        for (int rr = 0; rr < 2; rr++) {
            int m = m0 + wm + mt * 16 + gid + rr * 8;
#pragma unroll
            for (int nt = 0; nt < 4; nt++) {
                int col = n0 + wn + nt * 8 + tig * 2;
                float v0 = (acc[mt][nt][rr * 2 + 0] + bias[col]) * scale;
                float v1 = (acc[mt][nt][rr * 2 + 1] + bias[col + 1]) * scale;
                if (headmode) {
                    int bb = m >> 11, t = m & (Tn - 1);
                    int hh = col >> 6, dd = col & 63;
                    size_t idx = ((((size_t)bb * Hh + hh) * Tn + t) << 6) + dd;
                    __nv_bfloat16 h0, l0, h1, l1;
                    bf16_split(v0, h0, l0);
                    bf16_split(v1, h1, l1);
                    *(ushort2*)&Phi[idx] = make_ushort2(__bfloat16_as_ushort(h0),
                                                        __bfloat16_as_ushort(h1));
                    *(ushort2*)&Plo[idx] = make_ushort2(__bfloat16_as_ushort(l0),
                                                        __bfloat16_as_ushort(l1));
                } else {
                    *(float2*)&C[(size_t)m * N + col] = make_float2(v0, v1);
                }
            }
        }
    }
}

// ---------------------------------------------------------------------------
// Tensor-core masked flash attention (double-bf16), v2:
// ldmatrix fragment loads (V via .trans — no manual transpose),
// cp.async double-buffered K/V stages with active-tile prefetch list.
// 128 threads / 4 warps; warp = 16 q rows; 64q x 64k tiles.
// Stage layout: 4 planes (Kh,Kl,Vh,Vl) x [64 rows x 128B], XOR-16B swizzle.
// ---------------------------------------------------------------------------
#define ATTN_DSMEM 65536   // 2 stages x 4 planes x 8KB

__device__ __forceinline__ uint32_t sw_off(int row, int colB) {
    return (uint32_t)((row << 7) + (colB ^ ((row & 7) << 4)));
}

__global__ __launch_bounds__(128)
void attn_mma(const __nv_bfloat16* __restrict__ Qh, const __nv_bfloat16* __restrict__ Ql,
              const __nv_bfloat16* __restrict__ Kh, const __nv_bfloat16* __restrict__ Kl,
              const __nv_bfloat16* __restrict__ Vh, const __nv_bfloat16* __restrict__ Vl,
              float* __restrict__ C, const int* __restrict__ bs_ptr) {
    extern __shared__ char asmem[];
    const uint32_t sb = smem_u32(asmem);

    int bs = 4;
    if (bs_ptr) {
        int v = *bs_ptr;
        if (v >= 1 && v <= Tn) bs = v;
    }

    const int tid = threadIdx.x, w = tid >> 5, lane = tid & 31;
    const int gid = lane >> 2, tig = lane & 3;
    const int t16 = lane & 15;
    const int qt = gridDim.x - 1 - blockIdx.x;   // heavy tiles first
    const int h = blockIdx.y, b = blockIdx.z;
    const int q0 = qt * 64;
    const size_t base = ((size_t)b * Hh + h) * Tn * HD;

    // Q fragments hoisted from global (once)
    const int r0 = q0 + w * 16 + gid;
    uint32_t qfh[4][4], qfl[4][4];
#pragma unroll
    for (int kc = 0; kc < 4; kc++) {
        const size_t o = base + (size_t)r0 * HD + kc * 16 + tig * 2;
        qfh[kc][0] = *(const uint32_t*)(Qh + o);
        qfh[kc][1] = *(const uint32_t*)(Qh + o + 8 * HD);
        qfh[kc][2] = *(const uint32_t*)(Qh + o + 8);
        qfh[kc][3] = *(const uint32_t*)(Qh + o + 8 * HD + 8);
        qfl[kc][0] = *(const uint32_t*)(Ql + o);
        qfl[kc][1] = *(const uint32_t*)(Ql + o + 8 * HD);
        qfl[kc][2] = *(const uint32_t*)(Ql + o + 8);
        qfl[kc][3] = *(const uint32_t*)(Ql + o + 8 * HD + 8);
    }

    const bool x0q = (r0 >= NHALF);
    const int bq0 = (x0q ? r0 - NHALF : r0) / bs;
    const int bq1 = (x0q ? r0 + 8 - NHALF : r0 + 8) / bs;

    float cac[8][4];
#pragma unroll
    for (int i = 0; i < 8; i++)
#pragma unroll
        for (int j = 0; j < 4; j++) cac[i][j] = 0.0f;
    float mi0 = -1e30f, mi1 = -1e30f, li0 = 0.0f, li1 = 0.0f;

    // Active k-tile list
    const int bqlo = (x0q ? q0 - NHALF : q0) / bs;
    const int bqhi = (x0q ? q0 + 63 - NHALF : q0 + 63) / bs;
    int kts[Tn / 64];
    int nkt = 0;
    for (int kt = 0; kt < Tn / 64; kt++) {
        const int k0 = kt * 64;
        const bool x0k = (k0 >= NHALF);
        int bklo = (x0k ? k0 - NHALF : k0) / bs;
        int bkhi = (x0k ? k0 + 63 - NHALF : k0 + 63) / bs;
        bool any = (x0q == x0k && bqhi >= bklo && bkhi >= bqlo) ||
                   (!x0q && x0k && bqhi > bklo) ||
                   (x0q && x0k && bqhi >= bklo);
        if (any) kts[nkt++] = kt;
    }

    auto fill = [&](int kt, int st) {
        const int k0 = kt * 64;
        const __nv_bfloat16* gp[4] = {Kh + base + (size_t)k0 * HD,
                                      Kl + base + (size_t)k0 * HD,
                                      Vh + base + (size_t)k0 * HD,
                                      Vl + base + (size_t)k0 * HD};
#pragma unroll
        for (int i = 0; i < 16; i++) {
            int lin = tid + 128 * i;
            int pl = lin >> 9, wi = lin & 511;
            int row = wi >> 3, c = wi & 7;
            uint32_t dst = sb + st * 32768 + pl * 8192 + sw_off(row, c << 4);
            cp16(dst, gp[pl] + row * HD + c * 8);
        }
        asm volatile("cp.async.commit_group;\n");
    };

    if (nkt > 0) fill(kts[0], 0);

    for (int i = 0; i < nkt; i++) {
        const int st = i & 1;
        if (i + 1 < nkt) {
            fill(kts[i + 1], st ^ 1);
            asm volatile("cp.async.wait_group 1;\n");
        } else {
            asm volatile("cp.async.wait_group 0;\n");
        }
        __syncthreads();

        const int k0 = kts[i] * 64;
        const bool x0k = (k0 >= NHALF);
        const uint32_t khb = sb + st * 32768;
        const uint32_t klb = khb + 8192;
        const uint32_t vhb = khb + 16384;
        const uint32_t vlb = khb + 24576;

        // S = Q K^T (3-mma double-bf16, ldmatrix K frags)
        float sac[8][4];
#pragma unroll
        for (int ii = 0; ii < 8; ii++)
#pragma unroll
            for (int j = 0; j < 4; j++) sac[ii][j] = 0.0f;
#pragma unroll
        for (int kc = 0; kc < 4; kc++) {
#pragma unroll
            for (int nt = 0; nt < 8; nt++) {
                uint32_t off = sw_off(nt * 8 + (t16 & 7), kc * 32 + ((t16 >> 3) << 4));
                uint32_t bh0, bh1, bl0, bl1;
                ldsm_x2(bh0, bh1, khb + off);
                ldsm_x2(bl0, bl1, klb + off);
                mma_bf16(sac[nt], qfh[kc][0], qfh[kc][1], qfh[kc][2], qfh[kc][3], bh0, bh1);
                mma_bf16(sac[nt], qfh[kc][0], qfh[kc][1], qfh[kc][2], qfh[kc][3], bl0, bl1);
                mma_bf16(sac[nt], qfl[kc][0], qfl[kc][1], qfl[kc][2], qfl[kc][3], bh0, bh1);
            }
        }

        // Mask
#pragma unroll
        for (int nt = 0; nt < 8; nt++) {
#pragma unroll
            for (int e = 0; e < 2; e++) {
                int col = k0 + nt * 8 + tig * 2 + e;
                int bk = (x0k ? col - NHALF : col) / bs;
                bool c0 = (bq0 == bk && x0q == x0k) || (bq0 > bk && x0k && !x0q) ||
                          (bq0 >= bk && x0k && x0q);
                bool c1 = (bq1 == bk && x0q == x0k) || (bq1 > bk && x0k && !x0q) ||
                          (bq1 >= bk && x0k && x0q);
                if (!c0) sac[nt][e] = -1e30f;
                if (!c1) sac[nt][2 + e] = -1e30f;
            }
        }

        // Online softmax
        float rm0 = -1e30f, rm1 = -1e30f;
#pragma unroll
        for (int nt = 0; nt < 8; nt++) {
            rm0 = fmaxf(rm0, fmaxf(sac[nt][0], sac[nt][1]));
            rm1 = fmaxf(rm1, fmaxf(sac[nt][2], sac[nt][3]));
        }
        rm0 = fmaxf(rm0, __shfl_xor_sync(0xffffffffu, rm0, 1));
        rm0 = fmaxf(rm0, __shfl_xor_sync(0xffffffffu, rm0, 2));
        rm1 = fmaxf(rm1, __shfl_xor_sync(0xffffffffu, rm1, 1));
        rm1 = fmaxf(rm1, __shfl_xor_sync(0xffffffffu, rm1, 2));
        float mn0 = fmaxf(mi0, rm0), mn1 = fmaxf(mi1, rm1);
        float f0 = __expf(mi0 - mn0), f1 = __expf(mi1 - mn1);
        mi0 = mn0; mi1 = mn1;
        float rs0 = 0.0f, rs1 = 0.0f;
#pragma unroll
        for (int nt = 0; nt < 8; nt++) {
            sac[nt][0] = __expf(sac[nt][0] - mn0);
            sac[nt][1] = __expf(sac[nt][1] - mn0);
            sac[nt][2] = __expf(sac[nt][2] - mn1);
            sac[nt][3] = __expf(sac[nt][3] - mn1);
            rs0 += sac[nt][0] + sac[nt][1];
            rs1 += sac[nt][2] + sac[nt][3];
        }
        rs0 += __shfl_xor_sync(0xffffffffu, rs0, 1);
        rs0 += __shfl_xor_sync(0xffffffffu, rs0, 2);
        rs1 += __shfl_xor_sync(0xffffffffu, rs1, 1);
        rs1 += __shfl_xor_sync(0xffffffffu, rs1, 2);
        li0 = li0 * f0 + rs0;
        li1 = li1 * f1 + rs1;
#pragma unroll
        for (int nd = 0; nd < 8; nd++) {
            cac[nd][0] *= f0; cac[nd][1] *= f0;
            cac[nd][2] *= f1; cac[nd][3] *= f1;
        }

        // P repack + PV (3-mma double-bf16, ldmatrix.trans V frags)
#pragma unroll
        for (int kc = 0; kc < 4; kc++) {
            const int nA = kc * 2, nB = kc * 2 + 1;
            uint32_t ph_[4], pl_[4];
            {
                __nv_bfloat16 hx, lx, hy, ly;
                bf16_split(sac[nA][0], hx, lx); bf16_split(sac[nA][1], hy, ly);
                ph_[0] = (uint32_t)__bfloat16_as_ushort(hx) |
                         ((uint32_t)__bfloat16_as_ushort(hy) << 16);
                pl_[0] = (uint32_t)__bfloat16_as_ushort(lx) |
                         ((uint32_t)__bfloat16_as_ushort(ly) << 16);
                bf16_split(sac[nA][2], hx, lx); bf16_split(sac[nA][3], hy, ly);
                ph_[1] = (uint32_t)__bfloat16_as_ushort(hx) |
                         ((uint32_t)__bfloat16_as_ushort(hy) << 16);
                pl_[1] = (uint32_t)__bfloat16_as_ushort(lx) |
                         ((uint32_t)__bfloat16_as_ushort(ly) << 16);
                bf16_split(sac[nB][0], hx, lx); bf16_split(sac[nB][1], hy, ly);
                ph_[2] = (uint32_t)__bfloat16_as_ushort(hx) |
                         ((uint32_t)__bfloat16_as_ushort(hy) << 16);
                pl_[2] = (uint32_t)__bfloat16_as_ushort(lx) |
                         ((uint32_t)__bfloat16_as_ushort(ly) << 16);
                bf16_split(sac[nB][2], hx, lx); bf16_split(sac[nB][3], hy, ly);
                ph_[3] = (uint32_t)__bfloat16_as_ushort(hx) |
                         ((uint32_t)__bfloat16_as_ushort(hy) << 16);
                pl_[3] = (uint32_t)__bfloat16_as_ushort(lx) |
                         ((uint32_t)__bfloat16_as_ushort(ly) << 16);
            }
#pragma unroll
            for (int nd = 0; nd < 8; nd++) {
                uint32_t off = sw_off(kc * 16 + t16, nd * 16);
                uint32_t bh0, bh1, bl0, bl1;
                ldsm_x2_t(bh0, bh1, vhb + off);
                ldsm_x2_t(bl0, bl1, vlb + off);
                mma_bf16(cac[nd], ph_[0], ph_[1], ph_[2], ph_[3], bh0, bh1);
                mma_bf16(cac[nd], ph_[0], ph_[1], ph_[2], ph_[3], bl0, bl1);
                mma_bf16(cac[nd], pl_[0], pl_[1], pl_[2], pl_[3], bh0, bh1);
            }
        }
        __syncthreads();   // stage reusable for next prefetch
    }

    // Epilogue: C[b][t][h*64+d]
    float il0 = 1.0f / li0, il1 = 1.0f / li1;
#pragma unroll
    for (int nd = 0; nd < 8; nd++) {
        int d = h * HD + nd * 8 + tig * 2;
        *(float2*)&C[((size_t)b * Tn + r0) * Dm + d] =
            make_float2(cac[nd][0] * il0, cac[nd][1] * il0);
        *(float2*)&C[((size_t)b * Tn + r0 + 8) * Dm + d] =
            make_float2(cac[nd][2] * il1, cac[nd][3] * il1);
    }
}

// ---------------------------------------------------------------------------
extern "C" void kernel_launch(void* const* d_in, const int* in_sizes, int n_in,
                              void* d_out, int out_size) {
    const float* x  = (const float*)d_in[0];
    const float* Wq = (const float*)d_in[1];
    const float* bq = (const float*)d_in[2];
    const float* Wk = (const float*)d_in[3];
    const float* bk = (const float*)d_in[4];
    const float* Wv = (const float*)d_in[5];
    const float* bv = (const float*)d_in[6];
    const float* Wo = (const float*)d_in[7];
    const float* bo = (const float*)d_in[8];
    const int* bsp  = (n_in > 9) ? (const int*)d_in[9] : nullptr;

    float* cb;
    cudaGetSymbolAddress((void**)&cb, g_C);
    __nv_bfloat16 *qh, *ql, *kh, *kl, *vh, *vl;
    cudaGetSymbolAddress((void**)&qh, g_Qh);
    cudaGetSymbolAddress((void**)&ql, g_Ql);
    cudaGetSymbolAddress((void**)&kh, g_Kh);
    cudaGetSymbolAddress((void**)&kl, g_Kl);
    cudaGetSymbolAddress((void**)&vh, g_Vh);
    cudaGetSymbolAddress((void**)&vl, g_Vl);

    __nv_bfloat16 *xh, *xl, *ch, *cl;
    __nv_bfloat16 *wqh, *wql, *wkh, *wkl, *wvh, *wvl, *woh, *wol;
    cudaGetSymbolAddress((void**)&xh, g_xhi);
    cudaGetSymbolAddress((void**)&xl, g_xlo);
    cudaGetSymbolAddress((void**)&ch, g_chi);
    cudaGetSymbolAddress((void**)&cl, g_clo);
    cudaGetSymbolAddress((void**)&wqh, g_wqh);
    cudaGetSymbolAddress((void**)&wql, g_wql);
    cudaGetSymbolAddress((void**)&wkh, g_wkh);
    cudaGetSymbolAddress((void**)&wkl, g_wkl);
    cudaGetSymbolAddress((void**)&wvh, g_wvh);
    cudaGetSymbolAddress((void**)&wvl, g_wvl);
    cudaGetSymbolAddress((void**)&woh, g_woh);
    cudaGetSymbolAddress((void**)&wol, g_wol);

    cudaFuncSetAttribute(gemm_bf16x3, cudaFuncAttributeMaxDynamicSharedMemorySize,
                         GEMM_SMEM);
    cudaFuncSetAttribute(attn_mma, cudaFuncAttributeMaxDynamicSharedMemorySize,
                         ATTN_DSMEM);

    const int M = Bz * Tn;
    const int nx4 = Bz * Tn * Dm / 4;

    split_rows<<<(nx4 + 255) / 256, 256>>>((const float4*)x, xh, xl, nx4);
    dim3 tg(Dm / 32, Dm / 32), tb(32, 8);
    split_T<<<tg, tb>>>(Wq, wqh, wql);
    split_T<<<tg, tb>>>(Wk, wkh, wkl);
    split_T<<<tg, tb>>>(Wv, wvh, wvl);
    split_T<<<tg, tb>>>(Wo, woh, wol);

    dim3 gg(Dm / 128, M / 128);
    const float qscale = 0.125f;  // hd^-0.5, hd=64

    gemm_bf16x3<<<gg, 256, GEMM_SMEM>>>(xh, xl, wqh, wql, bq, nullptr, qh, ql,
                                        M, Dm, Dm, qscale, 1);
    gemm_bf16x3<<<gg, 256, GEMM_SMEM>>>(xh, xl, wkh, wkl, bk, nullptr, kh, kl,
                                        M, Dm, Dm, 1.0f, 1);
    gemm_bf16x3<<<gg, 256, GEMM_SMEM>>>(xh, xl, wvh, wvl, bv, nullptr, vh, vl,
                                        M, Dm, Dm, 1.0f, 1);

    dim3 ga(Tn / 64, Hh, Bz);
    attn_mma<<<ga, 128, ATTN_DSMEM>>>(qh, ql, kh, kl, vh, vl, cb, bsp);

    split_rows<<<(nx4 + 255) / 256, 256>>>((const float4*)cb, ch, cl, nx4);
    gemm_bf16x3<<<gg, 256, GEMM_SMEM>>>(ch, cl, woh, wol, bo, (float*)d_out,
                                        nullptr, nullptr, M, Dm, Dm, 1.0f, 0);
}

// round 11
// speedup vs baseline: 2.8512x; 1.0874x over previous
#include <cuda_runtime.h>
#include <cuda_bf16.h>
#include <math.h>
#include <stdint.h>

#define Bz 4
#define Tn 2048
#define Dm 1024
#define Hh 16
#define HD 64
#define NHALF 1024   // Tn/2

// Scratch (device globals — allocation-free per harness rules)
__device__ float g_C[(size_t)Bz * Tn * Dm];

// Q/K/V bf16 split planes [b,h,t,d]
__device__ __nv_bfloat16 g_Qh[(size_t)Bz * Hh * Tn * HD];
__device__ __nv_bfloat16 g_Ql[(size_t)Bz * Hh * Tn * HD];
__device__ __nv_bfloat16 g_Kh[(size_t)Bz * Hh * Tn * HD];
__device__ __nv_bfloat16 g_Kl[(size_t)Bz * Hh * Tn * HD];
__device__ __nv_bfloat16 g_Vh[(size_t)Bz * Hh * Tn * HD];
__device__ __nv_bfloat16 g_Vl[(size_t)Bz * Hh * Tn * HD];

// x / ctx bf16 split planes
__device__ __nv_bfloat16 g_xhi[(size_t)Bz * Tn * Dm];
__device__ __nv_bfloat16 g_xlo[(size_t)Bz * Tn * Dm];
__device__ __nv_bfloat16 g_chi[(size_t)Bz * Tn * Dm];
__device__ __nv_bfloat16 g_clo[(size_t)Bz * Tn * Dm];
// weights TRANSPOSED [N][K], split planes
__device__ __nv_bfloat16 g_wqh[(size_t)Dm * Dm];
__device__ __nv_bfloat16 g_wql[(size_t)Dm * Dm];
__device__ __nv_bfloat16 g_wkh[(size_t)Dm * Dm];
__device__ __nv_bfloat16 g_wkl[(size_t)Dm * Dm];
__device__ __nv_bfloat16 g_wvh[(size_t)Dm * Dm];
__device__ __nv_bfloat16 g_wvl[(size_t)Dm * Dm];
__device__ __nv_bfloat16 g_woh[(size_t)Dm * Dm];
__device__ __nv_bfloat16 g_wol[(size_t)Dm * Dm];

// ---------------------------------------------------------------------------
__device__ __forceinline__ void bf16_split(float x, __nv_bfloat16& h, __nv_bfloat16& l) {
    h = __float2bfloat16_rn(x);
    l = __float2bfloat16_rn(x - __bfloat162float(h));
}

__global__ __launch_bounds__(256)
void split_rows(const float4* __restrict__ in, __nv_bfloat16* __restrict__ hi,
                __nv_bfloat16* __restrict__ lo, int n4) {
    int i = blockIdx.x * blockDim.x + threadIdx.x;
    if (i >= n4) return;
    float4 v = in[i];
    __nv_bfloat16 h[4], l[4];
    bf16_split(v.x, h[0], l[0]);
    bf16_split(v.y, h[1], l[1]);
    bf16_split(v.z, h[2], l[2]);
    bf16_split(v.w, h[3], l[3]);
    ushort4 hv = make_ushort4(__bfloat16_as_ushort(h[0]), __bfloat16_as_ushort(h[1]),
                              __bfloat16_as_ushort(h[2]), __bfloat16_as_ushort(h[3]));
    ushort4 lv = make_ushort4(__bfloat16_as_ushort(l[0]), __bfloat16_as_ushort(l[1]),
                              __bfloat16_as_ushort(l[2]), __bfloat16_as_ushort(l[3]));
    ((ushort4*)hi)[i] = hv;
    ((ushort4*)lo)[i] = lv;
}

// Transpose+split all 4 weights in one launch (blockIdx.z selects the weight).
__global__ __launch_bounds__(256)
void split_T4(const float* __restrict__ W0, const float* __restrict__ W1,
              const float* __restrict__ W2, const float* __restrict__ W3,
              __nv_bfloat16* __restrict__ H0, __nv_bfloat16* __restrict__ L0,
              __nv_bfloat16* __restrict__ H1, __nv_bfloat16* __restrict__ L1,
              __nv_bfloat16* __restrict__ H2, __nv_bfloat16* __restrict__ L2,
              __nv_bfloat16* __restrict__ H3, __nv_bfloat16* __restrict__ L3) {
    const float* W = (blockIdx.z == 0) ? W0 : (blockIdx.z == 1) ? W1
                   : (blockIdx.z == 2) ? W2 : W3;
    __nv_bfloat16* hi = (blockIdx.z == 0) ? H0 : (blockIdx.z == 1) ? H1
                      : (blockIdx.z == 2) ? H2 : H3;
    __nv_bfloat16* lo = (blockIdx.z == 0) ? L0 : (blockIdx.z == 1) ? L1
                      : (blockIdx.z == 2) ? L2 : L3;
    __shared__ float tile[32][33];
    int tx = threadIdx.x, ty = threadIdx.y;
    int nb = blockIdx.x * 32, kb = blockIdx.y * 32;
#pragma unroll
    for (int j = 0; j < 32; j += 8)
        tile[ty + j][tx] = W[(size_t)(kb + ty + j) * Dm + nb + tx];
    __syncthreads();
#pragma unroll
    for (int j = 0; j < 32; j += 8) {
        int n = nb + ty + j, k = kb + tx;
        __nv_bfloat16 h, l;
        bf16_split(tile[tx][ty + j], h, l);
        hi[(size_t)n * Dm + k] = h;
        lo[(size_t)n * Dm + k] = l;
    }
}

// ---------------------------------------------------------------------------
// Shared low-level helpers
// ---------------------------------------------------------------------------
__device__ __forceinline__ uint32_t smem_u32(const void* p) {
    uint32_t a;
    asm("{ .reg .u64 t; cvta.to.shared.u64 t, %1; cvt.u32.u64 %0, t; }"
        : "=r"(a) : "l"(p));
    return a;
}

__device__ __forceinline__ void cp16(uint32_t dst, const void* src) {
    asm volatile("cp.async.cg.shared.global [%0], [%1], 16;\n" :: "r"(dst), "l"(src));
}

__device__ __forceinline__ void mma_bf16(float c[4], uint32_t a0, uint32_t a1,
                                         uint32_t a2, uint32_t a3,
                                         uint32_t b0, uint32_t b1) {
    asm volatile(
        "mma.sync.aligned.m16n8k16.row.col.f32.bf16.bf16.f32 "
        "{%0,%1,%2,%3}, {%4,%5,%6,%7}, {%8,%9}, {%0,%1,%2,%3};\n"
        : "+f"(c[0]), "+f"(c[1]), "+f"(c[2]), "+f"(c[3])
        : "r"(a0), "r"(a1), "r"(a2), "r"(a3), "r"(b0), "r"(b1));
}

__device__ __forceinline__ void ldsm_x2(uint32_t& r0, uint32_t& r1, uint32_t addr) {
    asm volatile("ldmatrix.sync.aligned.m8n8.x2.shared.b16 {%0,%1}, [%2];"
                 : "=r"(r0), "=r"(r1) : "r"(addr));
}
__device__ __forceinline__ void ldsm_x2_t(uint32_t& r0, uint32_t& r1, uint32_t addr) {
    asm volatile("ldmatrix.sync.aligned.m8n8.x2.trans.shared.b16 {%0,%1}, [%2];"
                 : "=r"(r0), "=r"(r1) : "r"(addr));
}
__device__ __forceinline__ void ldsm_x4(uint32_t& r0, uint32_t& r1, uint32_t& r2,
                                        uint32_t& r3, uint32_t addr) {
    asm volatile("ldmatrix.sync.aligned.m8n8.x4.shared.b16 {%0,%1,%2,%3}, [%4];"
                 : "=r"(r0), "=r"(r1), "=r"(r2), "=r"(r3) : "r"(addr));
}

// ---------------------------------------------------------------------------
// 3x-bf16 GEMM, v2: ldmatrix fragment loads.
// Smem plane: [128 rows][32 bf16 = 64B], swizzle off = row*64 + ((c^(row&3))<<4).
// 128x128 CTA, BK=32, 256 thr (8 warps 2x4), warp tile 64x32.
// ---------------------------------------------------------------------------
#define GPL 8192                      // plane bytes
#define GSTAGE (4 * GPL)              // stage bytes
#define GEMM_SMEM (2 * GSTAGE)

__global__ __launch_bounds__(256, 2)
void gemm_bf16x3(const __nv_bfloat16* __restrict__ Ahi,
                 const __nv_bfloat16* __restrict__ Alo,
                 const __nv_bfloat16* __restrict__ Bhi,
                 const __nv_bfloat16* __restrict__ Blo,
                 const float* __restrict__ bias, float* __restrict__ C,
                 __nv_bfloat16* __restrict__ Phi, __nv_bfloat16* __restrict__ Plo,
                 int M, int N, int K, float scale, int headmode) {
    extern __shared__ char smg[];
    const uint32_t sb = smem_u32(smg);

    const int tid = threadIdx.x;
    const int m0 = blockIdx.y * 128, n0 = blockIdx.x * 128;
    const int w = tid >> 5, lane = tid & 31;
    const int gid = lane >> 2, tig = lane & 3;
    const int m8 = lane & 7, sel = lane >> 3;
    const int wm = (w & 1) * 64, wn = (w >> 1) * 32;

    float acc[4][4][4];
#pragma unroll
    for (int i = 0; i < 4; i++)
#pragma unroll
        for (int j = 0; j < 4; j++)
#pragma unroll
            for (int c = 0; c < 4; c++) acc[i][j][c] = 0.0f;

    const __nv_bfloat16* gplanes[4] = {Ahi, Alo, Bhi, Blo};

    auto issue_tile = [&](int k0, int s) {
#pragma unroll
        for (int i = 0; i < 8; i++) {
            int lin = tid + 256 * i;
            int plane = lin >> 9;
            int wi = lin & 511;
            int row = wi >> 2, c = wi & 3;
            int grow = (plane < 2 ? m0 : n0) + row;
            uint32_t dst = sb + s * GSTAGE + plane * GPL + row * 64 +
                           (((uint32_t)(c ^ (row & 3))) << 4);
            cp16(dst, gplanes[plane] + (size_t)grow * K + k0 + c * 8);
        }
        asm volatile("cp.async.commit_group;\n");
    };

    issue_tile(0, 0);
    int cur = 0;

    for (int k0 = 0; k0 < K; k0 += 32) {
        if (k0 + 32 < K) {
            issue_tile(k0 + 32, cur ^ 1);
            asm volatile("cp.async.wait_group 1;\n");
        } else {
            asm volatile("cp.async.wait_group 0;\n");
        }
        __syncthreads();

        const uint32_t ahb = sb + cur * GSTAGE;
        const uint32_t alb = ahb + GPL;
        const uint32_t bhb = ahb + 2 * GPL;
        const uint32_t blb = ahb + 3 * GPL;

#pragma unroll
        for (int kk = 0; kk < 2; kk++) {
            // B fragments: 2 x ldmatrix.x4 per plane (nt pairs)
            uint32_t bh[4][2], bl[4][2];
#pragma unroll
            for (int np = 0; np < 2; np++) {
                int brow = wn + np * 16 + m8 + ((sel >> 1) << 3);
                int bc = kk * 2 + (sel & 1);
                uint32_t boff = (uint32_t)(brow * 64 + ((bc ^ (brow & 3)) << 4));
                ldsm_x4(bh[2 * np][0], bh[2 * np][1], bh[2 * np + 1][0],
                        bh[2 * np + 1][1], bhb + boff);
                ldsm_x4(bl[2 * np][0], bl[2 * np][1], bl[2 * np + 1][0],
                        bl[2 * np + 1][1], blb + boff);
            }
#pragma unroll
            for (int mt = 0; mt < 4; mt++) {
                int arow = wm + mt * 16 + m8 + ((sel & 1) << 3);
                int ac = kk * 2 + (sel >> 1);
                uint32_t aoff = (uint32_t)(arow * 64 + ((ac ^ (arow & 3)) << 4));
                uint32_t ah0, ah1, ah2, ah3, al0, al1, al2, al3;
                ldsm_x4(ah0, ah1, ah2, ah3, ahb + aoff);
                ldsm_x4(al0, al1, al2, al3, alb + aoff);
#pragma unroll
                for (int nt = 0; nt < 4; nt++) {
                    mma_bf16(acc[mt][nt], ah0, ah1, ah2, ah3, bh[nt][0], bh[nt][1]);
                    mma_bf16(acc[mt][nt], ah0, ah1, ah2, ah3, bl[nt][0], bl[nt][1]);
                    mma_bf16(acc[mt][nt], al0, al1, al2, al3, bh[nt][0], bh[nt][1]);
                }
            }
        }
        __syncthreads();
        cur ^= 1;
    }

#pragma unroll
    for (int mt = 0; mt < 4; mt++) {
#pragma unroll
        for (int rr = 0; rr < 2; rr++) {
            int m = m0 + wm + mt * 16 + gid + rr * 8;
#pragma unroll
            for (int nt = 0; nt < 4; nt++) {
                int col = n0 + wn + nt * 8 + tig * 2;
                float v0 = (acc[mt][nt][rr * 2 + 0] + bias[col]) * scale;
                float v1 = (acc[mt][nt][rr * 2 + 1] + bias[col + 1]) * scale;
                if (headmode) {
                    int bb = m >> 11, t = m & (Tn - 1);
                    int hh = col >> 6, dd = col & 63;
                    size_t idx = ((((size_t)bb * Hh + hh) * Tn + t) << 6) + dd;
                    __nv_bfloat16 h0, l0, h1, l1;
                    bf16_split(v0, h0, l0);
                    bf16_split(v1, h1, l1);
                    *(ushort2*)&Phi[idx] = make_ushort2(__bfloat16_as_ushort(h0),
                                                        __bfloat16_as_ushort(h1));
                    *(ushort2*)&Plo[idx] = make_ushort2(__bfloat16_as_ushort(l0),
                                                        __bfloat16_as_ushort(l1));
                } else {
                    *(float2*)&C[(size_t)m * N + col] = make_float2(v0, v1);
                }
            }
        }
    }
}

// ---------------------------------------------------------------------------
// Tensor-core masked flash attention (double-bf16), R10 proven version.
// ---------------------------------------------------------------------------
#define ATTN_DSMEM 65536   // 2 stages x 4 planes x 8KB

__device__ __forceinline__ uint32_t sw_off(int row, int colB) {
    return (uint32_t)((row << 7) + (colB ^ ((row & 7) << 4)));
}

__global__ __launch_bounds__(128)
void attn_mma(const __nv_bfloat16* __restrict__ Qh, const __nv_bfloat16* __restrict__ Ql,
              const __nv_bfloat16* __restrict__ Kh, const __nv_bfloat16* __restrict__ Kl,
              const __nv_bfloat16* __restrict__ Vh, const __nv_bfloat16* __restrict__ Vl,
              float* __restrict__ C, const int* __restrict__ bs_ptr) {
    extern __shared__ char asmem[];
    const uint32_t sb = smem_u32(asmem);

    int bs = 4;
    if (bs_ptr) {
        int v = *bs_ptr;
        if (v >= 1 && v <= Tn) bs = v;
    }

    const int tid = threadIdx.x, w = tid >> 5, lane = tid & 31;
    const int gid = lane >> 2, tig = lane & 3;
    const int t16 = lane & 15;
    const int qt = gridDim.x - 1 - blockIdx.x;
    const int h = blockIdx.y, b = blockIdx.z;
    const int q0 = qt * 64;
    const size_t base = ((size_t)b * Hh + h) * Tn * HD;

    const int r0 = q0 + w * 16 + gid;
    uint32_t qfh[4][4], qfl[4][4];
#pragma unroll
    for (int kc = 0; kc < 4; kc++) {
        const size_t o = base + (size_t)r0 * HD + kc * 16 + tig * 2;
        qfh[kc][0] = *(const uint32_t*)(Qh + o);
        qfh[kc][1] = *(const uint32_t*)(Qh + o + 8 * HD);
        qfh[kc][2] = *(const uint32_t*)(Qh + o + 8);
        qfh[kc][3] = *(const uint32_t*)(Qh + o + 8 * HD + 8);
        qfl[kc][0] = *(const uint32_t*)(Ql + o);
        qfl[kc][1] = *(const uint32_t*)(Ql + o + 8 * HD);
        qfl[kc][2] = *(const uint32_t*)(Ql + o + 8);
        qfl[kc][3] = *(const uint32_t*)(Ql + o + 8 * HD + 8);
    }

    const bool x0q = (r0 >= NHALF);
    const int bq0 = (x0q ? r0 - NHALF : r0) / bs;
    const int bq1 = (x0q ? r0 + 8 - NHALF : r0 + 8) / bs;

    float cac[8][4];
#pragma unroll
    for (int i = 0; i < 8; i++)
#pragma unroll
        for (int j = 0; j < 4; j++) cac[i][j] = 0.0f;
    float mi0 = -1e30f, mi1 = -1e30f, li0 = 0.0f, li1 = 0.0f;

    const int bqlo = (x0q ? q0 - NHALF : q0) / bs;
    const int bqhi = (x0q ? q0 + 63 - NHALF : q0 + 63) / bs;
    int kts[Tn / 64];
    int nkt = 0;
    for (int kt = 0; kt < Tn / 64; kt++) {
        const int k0 = kt * 64;
        const bool x0k = (k0 >= NHALF);
        int bklo = (x0k ? k0 - NHALF : k0) / bs;
        int bkhi = (x0k ? k0 + 63 - NHALF : k0 + 63) / bs;
        bool any = (x0q == x0k && bqhi >= bklo && bkhi >= bqlo) ||
                   (!x0q && x0k && bqhi > bklo) ||
                   (x0q && x0k && bqhi >= bklo);
        if (any) kts[nkt++] = kt;
    }

    auto fill = [&](int kt, int st) {
        const int k0 = kt * 64;
        const __nv_bfloat16* gp[4] = {Kh + base + (size_t)k0 * HD,
                                      Kl + base + (size_t)k0 * HD,
                                      Vh + base + (size_t)k0 * HD,
                                      Vl + base + (size_t)k0 * HD};
#pragma unroll
        for (int i = 0; i < 16; i++) {
            int lin = tid + 128 * i;
            int pl = lin >> 9, wi = lin & 511;
            int row = wi >> 3, c = wi & 7;
            uint32_t dst = sb + st * 32768 + pl * 8192 + sw_off(row, c << 4);
            cp16(dst, gp[pl] + row * HD + c * 8);
        }
        asm volatile("cp.async.commit_group;\n");
    };

    if (nkt > 0) fill(kts[0], 0);

    for (int i = 0; i < nkt; i++) {
        const int st = i & 1;
        if (i + 1 < nkt) {
            fill(kts[i + 1], st ^ 1);
            asm volatile("cp.async.wait_group 1;\n");
        } else {
            asm volatile("cp.async.wait_group 0;\n");
        }
        __syncthreads();

        const int k0 = kts[i] * 64;
        const bool x0k = (k0 >= NHALF);
        const uint32_t khb = sb + st * 32768;
        const uint32_t klb = khb + 8192;
        const uint32_t vhb = khb + 16384;
        const uint32_t vlb = khb + 24576;

        float sac[8][4];
#pragma unroll
        for (int ii = 0; ii < 8; ii++)
#pragma unroll
            for (int j = 0; j < 4; j++) sac[ii][j] = 0.0f;
#pragma unroll
        for (int kc = 0; kc < 4; kc++) {
#pragma unroll
            for (int nt = 0; nt < 8; nt++) {
                uint32_t off = sw_off(nt * 8 + (t16 & 7), kc * 32 + ((t16 >> 3) << 4));
                uint32_t bh0, bh1, bl0, bl1;
                ldsm_x2(bh0, bh1, khb + off);
                ldsm_x2(bl0, bl1, klb + off);
                mma_bf16(sac[nt], qfh[kc][0], qfh[kc][1], qfh[kc][2], qfh[kc][3], bh0, bh1);
                mma_bf16(sac[nt], qfh[kc][0], qfh[kc][1], qfh[kc][2], qfh[kc][3], bl0, bl1);
                mma_bf16(sac[nt], qfl[kc][0], qfl[kc][1], qfl[kc][2], qfl[kc][3], bh0, bh1);
            }
        }

#pragma unroll
        for (int nt = 0; nt < 8; nt++) {
#pragma unroll
            for (int e = 0; e < 2; e++) {
                int col = k0 + nt * 8 + tig * 2 + e;
                int bk = (x0k ? col - NHALF : col) / bs;
                bool c0 = (bq0 == bk && x0q == x0k) || (bq0 > bk && x0k && !x0q) ||
                          (bq0 >= bk && x0k && x0q);
                bool c1 = (bq1 == bk && x0q == x0k) || (bq1 > bk && x0k && !x0q) ||
                          (bq1 >= bk && x0k && x0q);
                if (!c0) sac[nt][e] = -1e30f;
                if (!c1) sac[nt][2 + e] = -1e30f;
            }
        }

        float rm0 = -1e30f, rm1 = -1e30f;
#pragma unroll
        for (int nt = 0; nt < 8; nt++) {
            rm0 = fmaxf(rm0, fmaxf(sac[nt][0], sac[nt][1]));
            rm1 = fmaxf(rm1, fmaxf(sac[nt][2], sac[nt][3]));
        }
        rm0 = fmaxf(rm0, __shfl_xor_sync(0xffffffffu, rm0, 1));
        rm0 = fmaxf(rm0, __shfl_xor_sync(0xffffffffu, rm0, 2));
        rm1 = fmaxf(rm1, __shfl_xor_sync(0xffffffffu, rm1, 1));
        rm1 = fmaxf(rm1, __shfl_xor_sync(0xffffffffu, rm1, 2));
        float mn0 = fmaxf(mi0, rm0), mn1 = fmaxf(mi1, rm1);
        float f0 = __expf(mi0 - mn0), f1 = __expf(mi1 - mn1);
        mi0 = mn0; mi1 = mn1;
        float rs0 = 0.0f, rs1 = 0.0f;
#pragma unroll
        for (int nt = 0; nt < 8; nt++) {
            sac[nt][0] = __expf(sac[nt][0] - mn0);
            sac[nt][1] = __expf(sac[nt][1] - mn0);
            sac[nt][2] = __expf(sac[nt][2] - mn1);
            sac[nt][3] = __expf(sac[nt][3] - mn1);
            rs0 += sac[nt][0] + sac[nt][1];
            rs1 += sac[nt][2] + sac[nt][3];
        }
        rs0 += __shfl_xor_sync(0xffffffffu, rs0, 1);
        rs0 += __shfl_xor_sync(0xffffffffu, rs0, 2);
        rs1 += __shfl_xor_sync(0xffffffffu, rs1, 1);
        rs1 += __shfl_xor_sync(0xffffffffu, rs1, 2);
        li0 = li0 * f0 + rs0;
        li1 = li1 * f1 + rs1;
#pragma unroll
        for (int nd = 0; nd < 8; nd++) {
            cac[nd][0] *= f0; cac[nd][1] *= f0;
            cac[nd][2] *= f1; cac[nd][3] *= f1;
        }

#pragma unroll
        for (int kc = 0; kc < 4; kc++) {
            const int nA = kc * 2, nB = kc * 2 + 1;
            uint32_t ph_[4], pl_[4];
            {
                __nv_bfloat16 hx, lx, hy, ly;
                bf16_split(sac[nA][0], hx, lx); bf16_split(sac[nA][1], hy, ly);
                ph_[0] = (uint32_t)__bfloat16_as_ushort(hx) |
                         ((uint32_t)__bfloat16_as_ushort(hy) << 16);
                pl_[0] = (uint32_t)__bfloat16_as_ushort(lx) |
                         ((uint32_t)__bfloat16_as_ushort(ly) << 16);
                bf16_split(sac[nA][2], hx, lx); bf16_split(sac[nA][3], hy, ly);
                ph_[1] = (uint32_t)__bfloat16_as_ushort(hx) |
                         ((uint32_t)__bfloat16_as_ushort(hy) << 16);
                pl_[1] = (uint32_t)__bfloat16_as_ushort(lx) |
                         ((uint32_t)__bfloat16_as_ushort(ly) << 16);
                bf16_split(sac[nB][0], hx, lx); bf16_split(sac[nB][1], hy, ly);
                ph_[2] = (uint32_t)__bfloat16_as_ushort(hx) |
                         ((uint32_t)__bfloat16_as_ushort(hy) << 16);
                pl_[2] = (uint32_t)__bfloat16_as_ushort(lx) |
                         ((uint32_t)__bfloat16_as_ushort(ly) << 16);
                bf16_split(sac[nB][2], hx, lx); bf16_split(sac[nB][3], hy, ly);
                ph_[3] = (uint32_t)__bfloat16_as_ushort(hx) |
                         ((uint32_t)__bfloat16_as_ushort(hy) << 16);
                pl_[3] = (uint32_t)__bfloat16_as_ushort(lx) |
                         ((uint32_t)__bfloat16_as_ushort(ly) << 16);
            }
#pragma unroll
            for (int nd = 0; nd < 8; nd++) {
                uint32_t off = sw_off(kc * 16 + t16, nd * 16);
                uint32_t bh0, bh1, bl0, bl1;
                ldsm_x2_t(bh0, bh1, vhb + off);
                ldsm_x2_t(bl0, bl1, vlb + off);
                mma_bf16(cac[nd], ph_[0], ph_[1], ph_[2], ph_[3], bh0, bh1);
                mma_bf16(cac[nd], ph_[0], ph_[1], ph_[2], ph_[3], bl0, bl1);
                mma_bf16(cac[nd], pl_[0], pl_[1], pl_[2], pl_[3], bh0, bh1);
            }
        }
        __syncthreads();
    }

    float il0 = 1.0f / li0, il1 = 1.0f / li1;
#pragma unroll
    for (int nd = 0; nd < 8; nd++) {
        int d = h * HD + nd * 8 + tig * 2;
        *(float2*)&C[((size_t)b * Tn + r0) * Dm + d] =
            make_float2(cac[nd][0] * il0, cac[nd][1] * il0);
        *(float2*)&C[((size_t)b * Tn + r0 + 8) * Dm + d] =
            make_float2(cac[nd][2] * il1, cac[nd][3] * il1);
    }
}

// ---------------------------------------------------------------------------
extern "C" void kernel_launch(void* const* d_in, const int* in_sizes, int n_in,
                              void* d_out, int out_size) {
    const float* x  = (const float*)d_in[0];
    const float* Wq = (const float*)d_in[1];
    const float* bq = (const float*)d_in[2];
    const float* Wk = (const float*)d_in[3];
    const float* bk = (const float*)d_in[4];
    const float* Wv = (const float*)d_in[5];
    const float* bv = (const float*)d_in[6];
    const float* Wo = (const float*)d_in[7];
    const float* bo = (const float*)d_in[8];
    const int* bsp  = (n_in > 9) ? (const int*)d_in[9] : nullptr;

    float* cb;
    cudaGetSymbolAddress((void**)&cb, g_C);
    __nv_bfloat16 *qh, *ql, *kh, *kl, *vh, *vl;
    cudaGetSymbolAddress((void**)&qh, g_Qh);
    cudaGetSymbolAddress((void**)&ql, g_Ql);
    cudaGetSymbolAddress((void**)&kh, g_Kh);
    cudaGetSymbolAddress((void**)&kl, g_Kl);
    cudaGetSymbolAddress((void**)&vh, g_Vh);
    cudaGetSymbolAddress((void**)&vl, g_Vl);

    __nv_bfloat16 *xh, *xl, *ch, *cl;
    __nv_bfloat16 *wqh, *wql, *wkh, *wkl, *wvh, *wvl, *woh, *wol;
    cudaGetSymbolAddress((void**)&xh, g_xhi);
    cudaGetSymbolAddress((void**)&xl, g_xlo);
    cudaGetSymbolAddress((void**)&ch, g_chi);
    cudaGetSymbolAddress((void**)&cl, g_clo);
    cudaGetSymbolAddress((void**)&wqh, g_wqh);
    cudaGetSymbolAddress((void**)&wql, g_wql);
    cudaGetSymbolAddress((void**)&wkh, g_wkh);
    cudaGetSymbolAddress((void**)&wkl, g_wkl);
    cudaGetSymbolAddress((void**)&wvh, g_wvh);
    cudaGetSymbolAddress((void**)&wvl, g_wvl);
    cudaGetSymbolAddress((void**)&woh, g_woh);
    cudaGetSymbolAddress((void**)&wol, g_wol);

    cudaFuncSetAttribute(gemm_bf16x3, cudaFuncAttributeMaxDynamicSharedMemorySize,
                         GEMM_SMEM);
    cudaFuncSetAttribute(attn_mma, cudaFuncAttributeMaxDynamicSharedMemorySize,
                         ATTN_DSMEM);

    const int M = Bz * Tn;
    const int nx4 = Bz * Tn * Dm / 4;

    split_rows<<<(nx4 + 255) / 256, 256>>>((const float4*)x, xh, xl, nx4);
    dim3 tg(Dm / 32, Dm / 32, 4), tb(32, 8);
    split_T4<<<tg, tb>>>(Wq, Wk, Wv, Wo, wqh, wql, wkh, wkl, wvh, wvl, woh, wol);

    dim3 gg(Dm / 128, M / 128);
    const float qscale = 0.125f;  // hd^-0.5, hd=64

    gemm_bf16x3<<<gg, 256, GEMM_SMEM>>>(xh, xl, wqh, wql, bq, nullptr, qh, ql,
                                        M, Dm, Dm, qscale, 1);
    gemm_bf16x3<<<gg, 256, GEMM_SMEM>>>(xh, xl, wkh, wkl, bk, nullptr, kh, kl,
                                        M, Dm, Dm, 1.0f, 1);
    gemm_bf16x3<<<gg, 256, GEMM_SMEM>>>(xh, xl, wvh, wvl, bv, nullptr, vh, vl,
                                        M, Dm, Dm, 1.0f, 1);

    dim3 ga(Tn / 64, Hh, Bz);
    attn_mma<<<ga, 128, ATTN_DSMEM>>>(qh, ql, kh, kl, vh, vl, cb, bsp);

    split_rows<<<(nx4 + 255) / 256, 256>>>((const float4*)cb, ch, cl, nx4);
    gemm_bf16x3<<<gg, 256, GEMM_SMEM>>>(ch, cl, woh, wol, bo, (float*)d_out,
                                        nullptr, nullptr, M, Dm, Dm, 1.0f, 0);
}

// round 14
// speedup vs baseline: 2.8733x; 1.0078x over previous
#include <cuda_runtime.h>
#include <cuda_bf16.h>
#include <math.h>
#include <stdint.h>

#define Bz 4
#define Tn 2048
#define Dm 1024
#define Hh 16
#define HD 64
#define NHALF 1024   // Tn/2

// Scratch (device globals — allocation-free per harness rules)
__device__ float g_C[(size_t)Bz * Tn * Dm];

// Q/K/V bf16 split planes [b,h,t,d]
__device__ __nv_bfloat16 g_Qh[(size_t)Bz * Hh * Tn * HD];
__device__ __nv_bfloat16 g_Ql[(size_t)Bz * Hh * Tn * HD];
__device__ __nv_bfloat16 g_Kh[(size_t)Bz * Hh * Tn * HD];
__device__ __nv_bfloat16 g_Kl[(size_t)Bz * Hh * Tn * HD];
__device__ __nv_bfloat16 g_Vh[(size_t)Bz * Hh * Tn * HD];
__device__ __nv_bfloat16 g_Vl[(size_t)Bz * Hh * Tn * HD];

// x / ctx bf16 split planes
__device__ __nv_bfloat16 g_xhi[(size_t)Bz * Tn * Dm];
__device__ __nv_bfloat16 g_xlo[(size_t)Bz * Tn * Dm];
__device__ __nv_bfloat16 g_chi[(size_t)Bz * Tn * Dm];
__device__ __nv_bfloat16 g_clo[(size_t)Bz * Tn * Dm];
// weights TRANSPOSED [N][K], split planes
__device__ __nv_bfloat16 g_wqh[(size_t)Dm * Dm];
__device__ __nv_bfloat16 g_wql[(size_t)Dm * Dm];
__device__ __nv_bfloat16 g_wkh[(size_t)Dm * Dm];
__device__ __nv_bfloat16 g_wkl[(size_t)Dm * Dm];
__device__ __nv_bfloat16 g_wvh[(size_t)Dm * Dm];
__device__ __nv_bfloat16 g_wvl[(size_t)Dm * Dm];
__device__ __nv_bfloat16 g_woh[(size_t)Dm * Dm];
__device__ __nv_bfloat16 g_wol[(size_t)Dm * Dm];

// ---------------------------------------------------------------------------
__device__ __forceinline__ void bf16_split(float x, __nv_bfloat16& h, __nv_bfloat16& l) {
    h = __float2bfloat16_rn(x);
    l = __float2bfloat16_rn(x - __bfloat162float(h));
}

__global__ __launch_bounds__(256)
void split_rows(const float4* __restrict__ in, __nv_bfloat16* __restrict__ hi,
                __nv_bfloat16* __restrict__ lo, int n4) {
    int i = blockIdx.x * blockDim.x + threadIdx.x;
    if (i >= n4) return;
    float4 v = in[i];
    __nv_bfloat16 h[4], l[4];
    bf16_split(v.x, h[0], l[0]);
    bf16_split(v.y, h[1], l[1]);
    bf16_split(v.z, h[2], l[2]);
    bf16_split(v.w, h[3], l[3]);
    ushort4 hv = make_ushort4(__bfloat16_as_ushort(h[0]), __bfloat16_as_ushort(h[1]),
                              __bfloat16_as_ushort(h[2]), __bfloat16_as_ushort(h[3]));
    ushort4 lv = make_ushort4(__bfloat16_as_ushort(l[0]), __bfloat16_as_ushort(l[1]),
                              __bfloat16_as_ushort(l[2]), __bfloat16_as_ushort(l[3]));
    ((ushort4*)hi)[i] = hv;
    ((ushort4*)lo)[i] = lv;
}

// Transpose+split all 4 weights in one launch (blockIdx.z selects the weight).
__global__ __launch_bounds__(256)
void split_T4(const float* __restrict__ W0, const float* __restrict__ W1,
              const float* __restrict__ W2, const float* __restrict__ W3,
              __nv_bfloat16* __restrict__ H0, __nv_bfloat16* __restrict__ L0,
              __nv_bfloat16* __restrict__ H1, __nv_bfloat16* __restrict__ L1,
              __nv_bfloat16* __restrict__ H2, __nv_bfloat16* __restrict__ L2,
              __nv_bfloat16* __restrict__ H3, __nv_bfloat16* __restrict__ L3) {
    const float* W = (blockIdx.z == 0) ? W0 : (blockIdx.z == 1) ? W1
                   : (blockIdx.z == 2) ? W2 : W3;
    __nv_bfloat16* hi = (blockIdx.z == 0) ? H0 : (blockIdx.z == 1) ? H1
                      : (blockIdx.z == 2) ? H2 : H3;
    __nv_bfloat16* lo = (blockIdx.z == 0) ? L0 : (blockIdx.z == 1) ? L1
                      : (blockIdx.z == 2) ? L2 : L3;
    __shared__ float tile[32][33];
    int tx = threadIdx.x, ty = threadIdx.y;
    int nb = blockIdx.x * 32, kb = blockIdx.y * 32;
#pragma unroll
    for (int j = 0; j < 32; j += 8)
        tile[ty + j][tx] = W[(size_t)(kb + ty + j) * Dm + nb + tx];
    __syncthreads();
#pragma unroll
    for (int j = 0; j < 32; j += 8) {
        int n = nb + ty + j, k = kb + tx;
        __nv_bfloat16 h, l;
        bf16_split(tile[tx][ty + j], h, l);
        hi[(size_t)n * Dm + k] = h;
        lo[(size_t)n * Dm + k] = l;
    }
}

// ---------------------------------------------------------------------------
// Shared low-level helpers
// ---------------------------------------------------------------------------
__device__ __forceinline__ uint32_t smem_u32(const void* p) {
    uint32_t a;
    asm("{ .reg .u64 t; cvta.to.shared.u64 t, %1; cvt.u32.u64 %0, t; }"
        : "=r"(a) : "l"(p));
    return a;
}

__device__ __forceinline__ void cp16(uint32_t dst, const void* src) {
    asm volatile("cp.async.cg.shared.global [%0], [%1], 16;\n" :: "r"(dst), "l"(src));
}

__device__ __forceinline__ void mma_bf16(float c[4], uint32_t a0, uint32_t a1,
                                         uint32_t a2, uint32_t a3,
                                         uint32_t b0, uint32_t b1) {
    asm volatile(
        "mma.sync.aligned.m16n8k16.row.col.f32.bf16.bf16.f32 "
        "{%0,%1,%2,%3}, {%4,%5,%6,%7}, {%8,%9}, {%0,%1,%2,%3};\n"
        : "+f"(c[0]), "+f"(c[1]), "+f"(c[2]), "+f"(c[3])
        : "r"(a0), "r"(a1), "r"(a2), "r"(a3), "r"(b0), "r"(b1));
}

__device__ __forceinline__ void ldsm_x2(uint32_t& r0, uint32_t& r1, uint32_t addr) {
    asm volatile("ldmatrix.sync.aligned.m8n8.x2.shared.b16 {%0,%1}, [%2];"
                 : "=r"(r0), "=r"(r1) : "r"(addr));
}
__device__ __forceinline__ void ldsm_x2_t(uint32_t& r0, uint32_t& r1, uint32_t addr) {
    asm volatile("ldmatrix.sync.aligned.m8n8.x2.trans.shared.b16 {%0,%1}, [%2];"
                 : "=r"(r0), "=r"(r1) : "r"(addr));
}
__device__ __forceinline__ void ldsm_x4(uint32_t& r0, uint32_t& r1, uint32_t& r2,
                                        uint32_t& r3, uint32_t addr) {
    asm volatile("ldmatrix.sync.aligned.m8n8.x4.shared.b16 {%0,%1,%2,%3}, [%4];"
                 : "=r"(r0), "=r"(r1), "=r"(r2), "=r"(r3) : "r"(addr));
}

// ---------------------------------------------------------------------------
// 3x-bf16 GEMM, v3: ldmatrix fragments + 3-stage cp.async pipeline
// (ONE __syncthreads per BK=32 chunk).
// Smem plane: [128 rows][32 bf16 = 64B], swizzle off = row*64 + ((c^(row&3))<<4).
// 128x128 CTA, BK=32, 256 thr (8 warps 2x4), warp tile 64x32.
// ---------------------------------------------------------------------------
#define GPL 8192                      // plane bytes
#define GSTAGE (4 * GPL)              // stage bytes (32 KB)
#define GSTAGES 3
#define GEMM_SMEM (GSTAGES * GSTAGE)  // 96 KB

__global__ __launch_bounds__(256, 2)
void gemm_bf16x3(const __nv_bfloat16* __restrict__ Ahi,
                 const __nv_bfloat16* __restrict__ Alo,
                 const __nv_bfloat16* __restrict__ Bhi,
                 const __nv_bfloat16* __restrict__ Blo,
                 const float* __restrict__ bias, float* __restrict__ C,
                 __nv_bfloat16* __restrict__ Phi, __nv_bfloat16* __restrict__ Plo,
                 int M, int N, int K, float scale, int headmode) {
    extern __shared__ char smg[];
    const uint32_t sb = smem_u32(smg);

    const int tid = threadIdx.x;
    const int m0 = blockIdx.y * 128, n0 = blockIdx.x * 128;
    const int w = tid >> 5, lane = tid & 31;
    const int gid = lane >> 2, tig = lane & 3;
    const int m8 = lane & 7, sel = lane >> 3;
    const int wm = (w & 1) * 64, wn = (w >> 1) * 32;

    float acc[4][4][4];
#pragma unroll
    for (int i = 0; i < 4; i++)
#pragma unroll
        for (int j = 0; j < 4; j++)
#pragma unroll
            for (int c = 0; c < 4; c++) acc[i][j][c] = 0.0f;

    const __nv_bfloat16* gplanes[4] = {Ahi, Alo, Bhi, Blo};

    auto issue_tile = [&](int k0, int s) {
#pragma unroll
        for (int i = 0; i < 8; i++) {
            int lin = tid + 256 * i;
            int plane = lin >> 9;
            int wi = lin & 511;
            int row = wi >> 2, c = wi & 3;
            int grow = (plane < 2 ? m0 : n0) + row;
            uint32_t dst = sb + s * GSTAGE + plane * GPL + row * 64 +
                           (((uint32_t)(c ^ (row & 3))) << 4);
            cp16(dst, gplanes[plane] + (size_t)grow * K + k0 + c * 8);
        }
        asm volatile("cp.async.commit_group;\n");
    };

    const int nch = K / 32;           // 32 chunks
    issue_tile(0, 0);
    issue_tile(32, 1);

    for (int i = 0; i < nch; i++) {
        if (i + 1 < nch) asm volatile("cp.async.wait_group 1;\n");
        else asm volatile("cp.async.wait_group 0;\n");
        __syncthreads();

        // prefetch stage i+2 (slot (i+2)%3 == slot (i-1)%3; all warps passed
        // the barrier above AFTER finishing compute(i-1), so overwrite is safe)
        if (i + 2 < nch) issue_tile((i + 2) * 32, (i + 2) % GSTAGES);

        const uint32_t ahb = sb + (i % GSTAGES) * GSTAGE;
        const uint32_t alb = ahb + GPL;
        const uint32_t bhb = ahb + 2 * GPL;
        const uint32_t blb = ahb + 3 * GPL;

#pragma unroll
        for (int kk = 0; kk < 2; kk++) {
            uint32_t bh[4][2], bl[4][2];
#pragma unroll
            for (int np = 0; np < 2; np++) {
                int brow = wn + np * 16 + m8 + ((sel >> 1) << 3);
                int bc = kk * 2 + (sel & 1);
                uint32_t boff = (uint32_t)(brow * 64 + ((bc ^ (brow & 3)) << 4));
                ldsm_x4(bh[2 * np][0], bh[2 * np][1], bh[2 * np + 1][0],
                        bh[2 * np + 1][1], bhb + boff);
                ldsm_x4(bl[2 * np][0], bl[2 * np][1], bl[2 * np + 1][0],
                        bl[2 * np + 1][1], blb + boff);
            }
#pragma unroll
            for (int mt = 0; mt < 4; mt++) {
                int arow = wm + mt * 16 + m8 + ((sel & 1) << 3);
                int ac = kk * 2 + (sel >> 1);
                uint32_t aoff = (uint32_t)(arow * 64 + ((ac ^ (arow & 3)) << 4));
                uint32_t ah0, ah1, ah2, ah3, al0, al1, al2, al3;
                ldsm_x4(ah0, ah1, ah2, ah3, ahb + aoff);
                ldsm_x4(al0, al1, al2, al3, alb + aoff);
#pragma unroll
                for (int nt = 0; nt < 4; nt++) {
                    mma_bf16(acc[mt][nt], ah0, ah1, ah2, ah3, bh[nt][0], bh[nt][1]);
                    mma_bf16(acc[mt][nt], ah0, ah1, ah2, ah3, bl[nt][0], bl[nt][1]);
                    mma_bf16(acc[mt][nt], al0, al1, al2, al3, bh[nt][0], bh[nt][1]);
                }
            }
        }
    }

#pragma unroll
    for (int mt = 0; mt < 4; mt++) {
#pragma unroll
        for (int rr = 0; rr < 2; rr++) {
            int m = m0 + wm + mt * 16 + gid + rr * 8;
#pragma unroll
            for (int nt = 0; nt < 4; nt++) {
                int col = n0 + wn + nt * 8 + tig * 2;
                float v0 = (acc[mt][nt][rr * 2 + 0] + bias[col]) * scale;
                float v1 = (acc[mt][nt][rr * 2 + 1] + bias[col + 1]) * scale;
                if (headmode) {
                    int bb = m >> 11, t = m & (Tn - 1);
                    int hh = col >> 6, dd = col & 63;
                    size_t idx = ((((size_t)bb * Hh + hh) * Tn + t) << 6) + dd;
                    __nv_bfloat16 h0, l0, h1, l1;
                    bf16_split(v0, h0, l0);
                    bf16_split(v1, h1, l1);
                    *(ushort2*)&Phi[idx] = make_ushort2(__bfloat16_as_ushort(h0),
                                                        __bfloat16_as_ushort(h1));
                    *(ushort2*)&Plo[idx] = make_ushort2(__bfloat16_as_ushort(l0),
                                                        __bfloat16_as_ushort(l1));
                } else {
                    *(float2*)&C[(size_t)m * N + col] = make_float2(v0, v1);
                }
            }
        }
    }
}

// ---------------------------------------------------------------------------
// Tensor-core masked flash attention (double-bf16), R10/R11 proven version.
// ---------------------------------------------------------------------------
#define ATTN_DSMEM 65536   // 2 stages x 4 planes x 8KB

__device__ __forceinline__ uint32_t sw_off(int row, int colB) {
    return (uint32_t)((row << 7) + (colB ^ ((row & 7) << 4)));
}

__global__ __launch_bounds__(128)
void attn_mma(const __nv_bfloat16* __restrict__ Qh, const __nv_bfloat16* __restrict__ Ql,
              const __nv_bfloat16* __restrict__ Kh, const __nv_bfloat16* __restrict__ Kl,
              const __nv_bfloat16* __restrict__ Vh, const __nv_bfloat16* __restrict__ Vl,
              float* __restrict__ C, const int* __restrict__ bs_ptr) {
    extern __shared__ char asmem[];
    const uint32_t sb = smem_u32(asmem);

    int bs = 4;
    if (bs_ptr) {
        int v = *bs_ptr;
        if (v >= 1 && v <= Tn) bs = v;
    }

    const int tid = threadIdx.x, w = tid >> 5, lane = tid & 31;
    const int gid = lane >> 2, tig = lane & 3;
    const int t16 = lane & 15;
    const int qt = gridDim.x - 1 - blockIdx.x;
    const int h = blockIdx.y, b = blockIdx.z;
    const int q0 = qt * 64;
    const size_t base = ((size_t)b * Hh + h) * Tn * HD;

    const int r0 = q0 + w * 16 + gid;
    uint32_t qfh[4][4], qfl[4][4];
#pragma unroll
    for (int kc = 0; kc < 4; kc++) {
        const size_t o = base + (size_t)r0 * HD + kc * 16 + tig * 2;
        qfh[kc][0] = *(const uint32_t*)(Qh + o);
        qfh[kc][1] = *(const uint32_t*)(Qh + o + 8 * HD);
        qfh[kc][2] = *(const uint32_t*)(Qh + o + 8);
        qfh[kc][3] = *(const uint32_t*)(Qh + o + 8 * HD + 8);
        qfl[kc][0] = *(const uint32_t*)(Ql + o);
        qfl[kc][1] = *(const uint32_t*)(Ql + o + 8 * HD);
        qfl[kc][2] = *(const uint32_t*)(Ql + o + 8);
        qfl[kc][3] = *(const uint32_t*)(Ql + o + 8 * HD + 8);
    }

    const bool x0q = (r0 >= NHALF);
    const int bq0 = (x0q ? r0 - NHALF : r0) / bs;
    const int bq1 = (x0q ? r0 + 8 - NHALF : r0 + 8) / bs;

    float cac[8][4];
#pragma unroll
    for (int i = 0; i < 8; i++)
#pragma unroll
        for (int j = 0; j < 4; j++) cac[i][j] = 0.0f;
    float mi0 = -1e30f, mi1 = -1e30f, li0 = 0.0f, li1 = 0.0f;

    const int bqlo = (x0q ? q0 - NHALF : q0) / bs;
    const int bqhi = (x0q ? q0 + 63 - NHALF : q0 + 63) / bs;
    int kts[Tn / 64];
    int nkt = 0;
    for (int kt = 0; kt < Tn / 64; kt++) {
        const int k0 = kt * 64;
        const bool x0k = (k0 >= NHALF);
        int bklo = (x0k ? k0 - NHALF : k0) / bs;
        int bkhi = (x0k ? k0 + 63 - NHALF : k0 + 63) / bs;
        bool any = (x0q == x0k && bqhi >= bklo && bkhi >= bqlo) ||
                   (!x0q && x0k && bqhi > bklo) ||
                   (x0q && x0k && bqhi >= bklo);
        if (any) kts[nkt++] = kt;
    }

    auto fill = [&](int kt, int st) {
        const int k0 = kt * 64;
        const __nv_bfloat16* gp[4] = {Kh + base + (size_t)k0 * HD,
                                      Kl + base + (size_t)k0 * HD,
                                      Vh + base + (size_t)k0 * HD,
                                      Vl + base + (size_t)k0 * HD};
#pragma unroll
        for (int i = 0; i < 16; i++) {
            int lin = tid + 128 * i;
            int pl = lin >> 9, wi = lin & 511;
            int row = wi >> 3, c = wi & 7;
            uint32_t dst = sb + st * 32768 + pl * 8192 + sw_off(row, c << 4);
            cp16(dst, gp[pl] + row * HD + c * 8);
        }
        asm volatile("cp.async.commit_group;\n");
    };

    if (nkt > 0) fill(kts[0], 0);

    for (int i = 0; i < nkt; i++) {
        const int st = i & 1;
        if (i + 1 < nkt) {
            fill(kts[i + 1], st ^ 1);
            asm volatile("cp.async.wait_group 1;\n");
        } else {
            asm volatile("cp.async.wait_group 0;\n");
        }
        __syncthreads();

        const int k0 = kts[i] * 64;
        const bool x0k = (k0 >= NHALF);
        const uint32_t khb = sb + st * 32768;
        const uint32_t klb = khb + 8192;
        const uint32_t vhb = khb + 16384;
        const uint32_t vlb = khb + 24576;

        float sac[8][4];
#pragma unroll
        for (int ii = 0; ii < 8; ii++)
#pragma unroll
            for (int j = 0; j < 4; j++) sac[ii][j] = 0.0f;
#pragma unroll
        for (int kc = 0; kc < 4; kc++) {
#pragma unroll
            for (int nt = 0; nt < 8; nt++) {
                uint32_t off = sw_off(nt * 8 + (t16 & 7), kc * 32 + ((t16 >> 3) << 4));
                uint32_t bh0, bh1, bl0, bl1;
                ldsm_x2(bh0, bh1, khb + off);
                ldsm_x2(bl0, bl1, klb + off);
                mma_bf16(sac[nt], qfh[kc][0], qfh[kc][1], qfh[kc][2], qfh[kc][3], bh0, bh1);
                mma_bf16(sac[nt], qfh[kc][0], qfh[kc][1], qfh[kc][2], qfh[kc][3], bl0, bl1);
                mma_bf16(sac[nt], qfl[kc][0], qfl[kc][1], qfl[kc][2], qfl[kc][3], bh0, bh1);
            }
        }

#pragma unroll
        for (int nt = 0; nt < 8; nt++) {
#pragma unroll
            for (int e = 0; e < 2; e++) {
                int col = k0 + nt * 8 + tig * 2 + e;
                int bk = (x0k ? col - NHALF : col) / bs;
                bool c0 = (bq0 == bk && x0q == x0k) || (bq0 > bk && x0k && !x0q) ||
                          (bq0 >= bk && x0k && x0q);
                bool c1 = (bq1 == bk && x0q == x0k) || (bq1 > bk && x0k && !x0q) ||
                          (bq1 >= bk && x0k && x0q);
                if (!c0) sac[nt][e] = -1e30f;
                if (!c1) sac[nt][2 + e] = -1e30f;
            }
        }

        float rm0 = -1e30f, rm1 = -1e30f;
#pragma unroll
        for (int nt = 0; nt < 8; nt++) {
            rm0 = fmaxf(rm0, fmaxf(sac[nt][0], sac[nt][1]));
            rm1 = fmaxf(rm1, fmaxf(sac[nt][2], sac[nt][3]));
        }
        rm0 = fmaxf(rm0, __shfl_xor_sync(0xffffffffu, rm0, 1));
        rm0 = fmaxf(rm0, __shfl_xor_sync(0xffffffffu, rm0, 2));
        rm1 = fmaxf(rm1, __shfl_xor_sync(0xffffffffu, rm1, 1));
        rm1 = fmaxf(rm1, __shfl_xor_sync(0xffffffffu, rm1, 2));
        float mn0 = fmaxf(mi0, rm0), mn1 = fmaxf(mi1, rm1);
        float f0 = __expf(mi0 - mn0), f1 = __expf(mi1 - mn1);
        mi0 = mn0; mi1 = mn1;
        float rs0 = 0.0f, rs1 = 0.0f;
#pragma unroll
        for (int nt = 0; nt < 8; nt++) {
            sac[nt][0] = __expf(sac[nt][0] - mn0);
            sac[nt][1] = __expf(sac[nt][1] - mn0);
            sac[nt][2] = __expf(sac[nt][2] - mn1);
            sac[nt][3] = __expf(sac[nt][3] - mn1);
            rs0 += sac[nt][0] + sac[nt][1];
            rs1 += sac[nt][2] + sac[nt][3];
        }
        rs0 += __shfl_xor_sync(0xffffffffu, rs0, 1);
        rs0 += __shfl_xor_sync(0xffffffffu, rs0, 2);
        rs1 += __shfl_xor_sync(0xffffffffu, rs1, 1);
        rs1 += __shfl_xor_sync(0xffffffffu, rs1, 2);
        li0 = li0 * f0 + rs0;
        li1 = li1 * f1 + rs1;
#pragma unroll
        for (int nd = 0; nd < 8; nd++) {
            cac[nd][0] *= f0; cac[nd][1] *= f0;
            cac[nd][2] *= f1; cac[nd][3] *= f1;
        }

#pragma unroll
        for (int kc = 0; kc < 4; kc++) {
            const int nA = kc * 2, nB = kc * 2 + 1;
            uint32_t ph_[4], pl_[4];
            {
                __nv_bfloat16 hx, lx, hy, ly;
                bf16_split(sac[nA][0], hx, lx); bf16_split(sac[nA][1], hy, ly);
                ph_[0] = (uint32_t)__bfloat16_as_ushort(hx) |
                         ((uint32_t)__bfloat16_as_ushort(hy) << 16);
                pl_[0] = (uint32_t)__bfloat16_as_ushort(lx) |
                         ((uint32_t)__bfloat16_as_ushort(ly) << 16);
                bf16_split(sac[nA][2], hx, lx); bf16_split(sac[nA][3], hy, ly);
                ph_[1] = (uint32_t)__bfloat16_as_ushort(hx) |
                         ((uint32_t)__bfloat16_as_ushort(hy) << 16);
                pl_[1] = (uint32_t)__bfloat16_as_ushort(lx) |
                         ((uint32_t)__bfloat16_as_ushort(ly) << 16);
                bf16_split(sac[nB][0], hx, lx); bf16_split(sac[nB][1], hy, ly);
                ph_[2] = (uint32_t)__bfloat16_as_ushort(hx) |
                         ((uint32_t)__bfloat16_as_ushort(hy) << 16);
                pl_[2] = (uint32_t)__bfloat16_as_ushort(lx) |
                         ((uint32_t)__bfloat16_as_ushort(ly) << 16);
                bf16_split(sac[nB][2], hx, lx); bf16_split(sac[nB][3], hy, ly);
                ph_[3] = (uint32_t)__bfloat16_as_ushort(hx) |
                         ((uint32_t)__bfloat16_as_ushort(hy) << 16);
                pl_[3] = (uint32_t)__bfloat16_as_ushort(lx) |
                         ((uint32_t)__bfloat16_as_ushort(ly) << 16);
            }
#pragma unroll
            for (int nd = 0; nd < 8; nd++) {
                uint32_t off = sw_off(kc * 16 + t16, nd * 16);
                uint32_t bh0, bh1, bl0, bl1;
                ldsm_x2_t(bh0, bh1, vhb + off);
                ldsm_x2_t(bl0, bl1, vlb + off);
                mma_bf16(cac[nd], ph_[0], ph_[1], ph_[2], ph_[3], bh0, bh1);
                mma_bf16(cac[nd], ph_[0], ph_[1], ph_[2], ph_[3], bl0, bl1);
                mma_bf16(cac[nd], pl_[0], pl_[1], pl_[2], pl_[3], bh0, bh1);
            }
        }
        __syncthreads();
    }

    float il0 = 1.0f / li0, il1 = 1.0f / li1;
#pragma unroll
    for (int nd = 0; nd < 8; nd++) {
        int d = h * HD + nd * 8 + tig * 2;
        *(float2*)&C[((size_t)b * Tn + r0) * Dm + d] =
            make_float2(cac[nd][0] * il0, cac[nd][1] * il0);
        *(float2*)&C[((size_t)b * Tn + r0 + 8) * Dm + d] =
            make_float2(cac[nd][2] * il1, cac[nd][3] * il1);
    }
}

// ---------------------------------------------------------------------------
extern "C" void kernel_launch(void* const* d_in, const int* in_sizes, int n_in,
                              void* d_out, int out_size) {
    const float* x  = (const float*)d_in[0];
    const float* Wq = (const float*)d_in[1];
    const float* bq = (const float*)d_in[2];
    const float* Wk = (const float*)d_in[3];
    const float* bk = (const float*)d_in[4];
    const float* Wv = (const float*)d_in[5];
    const float* bv = (const float*)d_in[6];
    const float* Wo = (const float*)d_in[7];
    const float* bo = (const float*)d_in[8];
    const int* bsp  = (n_in > 9) ? (const int*)d_in[9] : nullptr;

    float* cb;
    cudaGetSymbolAddress((void**)&cb, g_C);
    __nv_bfloat16 *qh, *ql, *kh, *kl, *vh, *vl;
    cudaGetSymbolAddress((void**)&qh, g_Qh);
    cudaGetSymbolAddress((void**)&ql, g_Ql);
    cudaGetSymbolAddress((void**)&kh, g_Kh);
    cudaGetSymbolAddress((void**)&kl, g_Kl);
    cudaGetSymbolAddress((void**)&vh, g_Vh);
    cudaGetSymbolAddress((void**)&vl, g_Vl);

    __nv_bfloat16 *xh, *xl, *ch, *cl;
    __nv_bfloat16 *wqh, *wql, *wkh, *wkl, *wvh, *wvl, *woh, *wol;
    cudaGetSymbolAddress((void**)&xh, g_xhi);
    cudaGetSymbolAddress((void**)&xl, g_xlo);
    cudaGetSymbolAddress((void**)&ch, g_chi);
    cudaGetSymbolAddress((void**)&cl, g_clo);
    cudaGetSymbolAddress((void**)&wqh, g_wqh);
    cudaGetSymbolAddress((void**)&wql, g_wql);
    cudaGetSymbolAddress((void**)&wkh, g_wkh);
    cudaGetSymbolAddress((void**)&wkl, g_wkl);
    cudaGetSymbolAddress((void**)&wvh, g_wvh);
    cudaGetSymbolAddress((void**)&wvl, g_wvl);
    cudaGetSymbolAddress((void**)&woh, g_woh);
    cudaGetSymbolAddress((void**)&wol, g_wol);

    cudaFuncSetAttribute(gemm_bf16x3, cudaFuncAttributeMaxDynamicSharedMemorySize,
                         GEMM_SMEM);
    cudaFuncSetAttribute(attn_mma, cudaFuncAttributeMaxDynamicSharedMemorySize,
                         ATTN_DSMEM);

    const int M = Bz * Tn;
    const int nx4 = Bz * Tn * Dm / 4;

    split_rows<<<(nx4 + 255) / 256, 256>>>((const float4*)x, xh, xl, nx4);
    dim3 tg(Dm / 32, Dm / 32, 4), tb(32, 8);
    split_T4<<<tg, tb>>>(Wq, Wk, Wv, Wo, wqh, wql, wkh, wkl, wvh, wvl, woh, wol);

    dim3 gg(Dm / 128, M / 128);
    const float qscale = 0.125f;  // hd^-0.5, hd=64

    gemm_bf16x3<<<gg, 256, GEMM_SMEM>>>(xh, xl, wqh, wql, bq, nullptr, qh, ql,
                                        M, Dm, Dm, qscale, 1);
    gemm_bf16x3<<<gg, 256, GEMM_SMEM>>>(xh, xl, wkh, wkl, bk, nullptr, kh, kl,
                                        M, Dm, Dm, 1.0f, 1);
    gemm_bf16x3<<<gg, 256, GEMM_SMEM>>>(xh, xl, wvh, wvl, bv, nullptr, vh, vl,
                                        M, Dm, Dm, 1.0f, 1);

    dim3 ga(Tn / 64, Hh, Bz);
    attn_mma<<<ga, 128, ATTN_DSMEM>>>(qh, ql, kh, kl, vh, vl, cb, bsp);

    split_rows<<<(nx4 + 255) / 256, 256>>>((const float4*)cb, ch, cl, nx4);
    gemm_bf16x3<<<gg, 256, GEMM_SMEM>>>(ch, cl, woh, wol, bo, (float*)d_out,
                                        nullptr, nullptr, M, Dm, Dm, 1.0f, 0);
}